// round 4
// baseline (speedup 1.0000x reference)
#include <cuda_runtime.h>
#include <cstddef>

#define T_LEN   2048
#define D_DIM   3584
#define NHEADS  28
#define KVH     4
#define HD      128
#define GRP     7          // NHEADS / KVH
#define QCOLS   (NHEADS*HD)   // 3584
#define KCOLS   (KVH*HD)      // 512
#define SCALE_ATTN 0.08838834764831845f  // 1/sqrt(128)

// -------- scratch (no cudaMalloc allowed) --------
__device__ float g_q [T_LEN * NHEADS * HD];   // (t, n, h)
__device__ float g_k [T_LEN * KVH    * HD];   // (t, kh, h)
__device__ float g_v [T_LEN * KVH    * HD];
__device__ float g_ao[T_LEN * NHEADS * HD];   // attention output (t, n, h)

// =====================================================================
// GEMM: C[M x Ncols] = A[M x K] * B[K x Ncols] (+ bias[Ncols])
// 128x128 tile, BK=8, 256 threads, 8x8 per thread.  M,Ncols,K all % tiles.
// =====================================================================
__global__ __launch_bounds__(256)
void gemm_bias_kernel(const float* __restrict__ A, const float* __restrict__ B,
                      const float* __restrict__ bias, float* __restrict__ C,
                      int M, int Ncols, int K)
{
    __shared__ float As[8][132];   // [k][m], padded
    __shared__ float Bs[8][128];   // [k][n]

    const int tid = threadIdx.x;
    const int tx  = tid & 15;       // 0..15 -> col group
    const int ty  = tid >> 4;       // 0..15 -> row group
    const int brow = blockIdx.y * 128;
    const int bcol = blockIdx.x * 128;

    // loader mapping
    const int arow = tid >> 1;            // 0..127
    const int acol = (tid & 1) * 4;       // 0 or 4
    const int brl  = tid >> 5;            // 0..7
    const int bcl  = (tid & 31) * 4;      // 0..124

    const float* Aptr = A + (size_t)(brow + arow) * K + acol;
    const float* Bptr = B + (size_t)brl * Ncols + bcol + bcl;

    float acc[8][8];
#pragma unroll
    for (int i = 0; i < 8; i++)
#pragma unroll
        for (int j = 0; j < 8; j++) acc[i][j] = 0.f;

    for (int k0 = 0; k0 < K; k0 += 8) {
        float4 av = *(const float4*)Aptr;  Aptr += 8;
        float4 bv = *(const float4*)Bptr;  Bptr += (size_t)8 * Ncols;

        __syncthreads();
        As[acol + 0][arow] = av.x;
        As[acol + 1][arow] = av.y;
        As[acol + 2][arow] = av.z;
        As[acol + 3][arow] = av.w;
        *(float4*)&Bs[brl][bcl] = bv;
        __syncthreads();

#pragma unroll
        for (int kk = 0; kk < 8; kk++) {
            float4 a0 = *(const float4*)&As[kk][ty * 8];
            float4 a1 = *(const float4*)&As[kk][ty * 8 + 4];
            float4 b0 = *(const float4*)&Bs[kk][tx * 8];
            float4 b1 = *(const float4*)&Bs[kk][tx * 8 + 4];
            float af[8] = {a0.x,a0.y,a0.z,a0.w,a1.x,a1.y,a1.z,a1.w};
            float bf[8] = {b0.x,b0.y,b0.z,b0.w,b1.x,b1.y,b1.z,b1.w};
#pragma unroll
            for (int i = 0; i < 8; i++)
#pragma unroll
                for (int j = 0; j < 8; j++)
                    acc[i][j] += af[i] * bf[j];
        }
    }

    // epilogue
    float bfrag[8];
    if (bias) {
#pragma unroll
        for (int j = 0; j < 8; j++) bfrag[j] = bias[bcol + tx * 8 + j];
    } else {
#pragma unroll
        for (int j = 0; j < 8; j++) bfrag[j] = 0.f;
    }
#pragma unroll
    for (int i = 0; i < 8; i++) {
        const int row = brow + ty * 8 + i;
        float* cp = C + (size_t)row * Ncols + bcol + tx * 8;
        float4 o0, o1;
        o0.x = acc[i][0] + bfrag[0]; o0.y = acc[i][1] + bfrag[1];
        o0.z = acc[i][2] + bfrag[2]; o0.w = acc[i][3] + bfrag[3];
        o1.x = acc[i][4] + bfrag[4]; o1.y = acc[i][5] + bfrag[5];
        o1.z = acc[i][6] + bfrag[6]; o1.w = acc[i][7] + bfrag[7];
        *(float4*)(cp)     = o0;
        *(float4*)(cp + 4) = o1;
    }
}

// =====================================================================
// RoPE: layout (t, heads, 128); pair (h, h+64) with sin/cos[t][h], h<64
// =====================================================================
__global__ __launch_bounds__(256)
void rope_kernel(float* __restrict__ q, const float* __restrict__ sinp,
                 const float* __restrict__ cosp, int heads)
{
    int idx = blockIdx.x * blockDim.x + threadIdx.x;
    int total = T_LEN * heads * 64;
    if (idx >= total) return;
    int h = idx & 63;
    int tmp = idx >> 6;
    int n = tmp % heads;
    int t = tmp / heads;
    float s = sinp[t * 64 + h];
    float c = cosp[t * 64 + h];
    float* p = q + ((size_t)t * heads + n) * HD + h;
    float x1 = p[0], x2 = p[64];
    p[0]  = x1 * c - x2 * s;
    p[64] = x2 * c + x1 * s;
}

// =====================================================================
// Flash attention: causal, GQA.  BM=BN=64, 256 threads.
// grid = (T/64, NHEADS).  dyn smem: Qs[64][132] Ks[64][132] Vs[64][128] Ps[64][65]
// =====================================================================
#define QK_STRIDE 132
#define P_STRIDE  65
#define FLASH_SMEM ((64*QK_STRIDE*2 + 64*128 + 64*P_STRIDE) * 4)

__global__ __launch_bounds__(256)
void flash_kernel()
{
    extern __shared__ float sm[];
    float* Qs = sm;                       // [64][132]
    float* Ks = Qs + 64 * QK_STRIDE;      // [64][132]
    float* Vs = Ks + 64 * QK_STRIDE;      // [64][128]
    float* Ps = Vs + 64 * 128;            // [64][65]

    const int br  = blockIdx.x;           // query row block
    const int n   = blockIdx.y;           // head
    const int kh  = n / GRP;
    const int tid = threadIdx.x;
    const int tx  = tid & 15;
    const int ty  = tid >> 4;
    const int r0  = ty * 4;               // local row base (S rows == O rows)

    // ---- load Q tile (pre-scaled) ----
    {
        const float* Qg = g_q + (size_t)(br * 64) * QCOLS + n * HD;
#pragma unroll
        for (int it = 0; it < 8; ++it) {
            int f  = tid + it * 256;          // 0..2047 (float4 index)
            int r  = f >> 5;
            int h4 = (f & 31) << 2;
            float4 v = *(const float4*)(Qg + (size_t)r * QCOLS + h4);
            v.x *= SCALE_ATTN; v.y *= SCALE_ATTN; v.z *= SCALE_ATTN; v.w *= SCALE_ATTN;
            *(float4*)(Qs + r * QK_STRIDE + h4) = v;
        }
    }

    float m_i[4], l_i[4], acc[4][8];
#pragma unroll
    for (int i = 0; i < 4; i++) {
        m_i[i] = -1e30f; l_i[i] = 0.f;
#pragma unroll
        for (int c = 0; c < 8; c++) acc[i][c] = 0.f;
    }

    for (int j = 0; j <= br; j++) {
        __syncthreads();  // prev iter done with Ks/Vs/Ps (also orders Q load)

        // ---- load K,V tile j ----
        {
            const float* Kg = g_k + (size_t)(j * 64) * KCOLS + kh * HD;
            const float* Vg = g_v + (size_t)(j * 64) * KCOLS + kh * HD;
#pragma unroll
            for (int it = 0; it < 8; ++it) {
                int f  = tid + it * 256;
                int r  = f >> 5;
                int h4 = (f & 31) << 2;
                float4 kv = *(const float4*)(Kg + (size_t)r * KCOLS + h4);
                *(float4*)(Ks + r * QK_STRIDE + h4) = kv;
                float4 vv = *(const float4*)(Vg + (size_t)r * KCOLS + h4);
                *(float4*)(Vs + r * 128 + h4) = vv;
            }
        }
        __syncthreads();

        // ---- S = Qs * Ks^T  (4x4 per thread) ----
        float s_[4][4];
#pragma unroll
        for (int i = 0; i < 4; i++)
#pragma unroll
            for (int jj = 0; jj < 4; jj++) s_[i][jj] = 0.f;

#pragma unroll 8
        for (int kk = 0; kk < 128; kk += 4) {
            float4 qf[4], kf[4];
#pragma unroll
            for (int i = 0; i < 4; i++)
                qf[i] = *(const float4*)(Qs + (r0 + i) * QK_STRIDE + kk);
#pragma unroll
            for (int jj = 0; jj < 4; jj++)
                kf[jj] = *(const float4*)(Ks + (tx * 4 + jj) * QK_STRIDE + kk);
#pragma unroll
            for (int i = 0; i < 4; i++)
#pragma unroll
                for (int jj = 0; jj < 4; jj++)
                    s_[i][jj] += qf[i].x * kf[jj].x + qf[i].y * kf[jj].y
                               + qf[i].z * kf[jj].z + qf[i].w * kf[jj].w;
        }

        // ---- causal mask on diagonal tile ----
        if (j == br) {
#pragma unroll
            for (int i = 0; i < 4; i++)
#pragma unroll
                for (int jj = 0; jj < 4; jj++)
                    if (tx * 4 + jj > r0 + i) s_[i][jj] = -1e30f;
        }

        // ---- online softmax (row reduce across tx: 16-lane shfl) ----
#pragma unroll
        for (int i = 0; i < 4; i++) {
            float tmax = fmaxf(fmaxf(s_[i][0], s_[i][1]), fmaxf(s_[i][2], s_[i][3]));
#pragma unroll
            for (int o = 8; o; o >>= 1)
                tmax = fmaxf(tmax, __shfl_xor_sync(0xffffffffu, tmax, o));
            float mnew = fmaxf(m_i[i], tmax);
            float p0 = __expf(s_[i][0] - mnew);
            float p1 = __expf(s_[i][1] - mnew);
            float p2 = __expf(s_[i][2] - mnew);
            float p3 = __expf(s_[i][3] - mnew);
            float rsum = p0 + p1 + p2 + p3;
#pragma unroll
            for (int o = 8; o; o >>= 1)
                rsum += __shfl_xor_sync(0xffffffffu, rsum, o);
            float alpha = __expf(m_i[i] - mnew);
            l_i[i] = l_i[i] * alpha + rsum;
            m_i[i] = mnew;
#pragma unroll
            for (int c = 0; c < 8; c++) acc[i][c] *= alpha;
            float* pr = Ps + (size_t)(r0 + i) * P_STRIDE + tx * 4;
            pr[0] = p0; pr[1] = p1; pr[2] = p2; pr[3] = p3;
        }
        __syncthreads();

        // ---- O += P * V  (4 rows x 8 cols per thread) ----
#pragma unroll 4
        for (int s = 0; s < 64; s++) {
            float p0 = Ps[(r0 + 0) * P_STRIDE + s];
            float p1 = Ps[(r0 + 1) * P_STRIDE + s];
            float p2 = Ps[(r0 + 2) * P_STRIDE + s];
            float p3 = Ps[(r0 + 3) * P_STRIDE + s];
            float4 v0 = *(const float4*)(Vs + s * 128 + tx * 8);
            float4 v1 = *(const float4*)(Vs + s * 128 + tx * 8 + 4);
            float vf[8] = {v0.x,v0.y,v0.z,v0.w,v1.x,v1.y,v1.z,v1.w};
#pragma unroll
            for (int c = 0; c < 8; c++) {
                acc[0][c] += p0 * vf[c];
                acc[1][c] += p1 * vf[c];
                acc[2][c] += p2 * vf[c];
                acc[3][c] += p3 * vf[c];
            }
        }
    }

    // ---- epilogue ----
#pragma unroll
    for (int i = 0; i < 4; i++) {
        float rl = 1.f / l_i[i];
        int row = br * 64 + r0 + i;
        float* op = g_ao + (size_t)row * QCOLS + n * HD + tx * 8;
        float4 o0, o1;
        o0.x = acc[i][0]*rl; o0.y = acc[i][1]*rl; o0.z = acc[i][2]*rl; o0.w = acc[i][3]*rl;
        o1.x = acc[i][4]*rl; o1.y = acc[i][5]*rl; o1.z = acc[i][6]*rl; o1.w = acc[i][7]*rl;
        *(float4*)(op)     = o0;
        *(float4*)(op + 4) = o1;
    }
}

// =====================================================================
extern "C" void kernel_launch(void* const* d_in, const int* in_sizes, int n_in,
                              void* d_out, int out_size)
{
    const float* x    = (const float*)d_in[0];
    // d_in[1] = attn_mask (deterministic causal tril) -- handled analytically
    const float* sinp = (const float*)d_in[2];
    const float* cosp = (const float*)d_in[3];
    const float* wq   = (const float*)d_in[4];
    const float* wk   = (const float*)d_in[5];
    const float* wv   = (const float*)d_in[6];
    const float* wo   = (const float*)d_in[7];
    const float* qb   = (const float*)d_in[8];
    const float* kb   = (const float*)d_in[9];
    const float* vb   = (const float*)d_in[10];
    float* out = (float*)d_out;

    float *qp, *kp, *vp, *aop;
    cudaGetSymbolAddress((void**)&qp,  g_q);
    cudaGetSymbolAddress((void**)&kp,  g_k);
    cudaGetSymbolAddress((void**)&vp,  g_v);
    cudaGetSymbolAddress((void**)&aop, g_ao);

    cudaFuncSetAttribute(flash_kernel,
                         cudaFuncAttributeMaxDynamicSharedMemorySize, FLASH_SMEM);

    // QKV projections (+bias)
    gemm_bias_kernel<<<dim3(QCOLS/128, T_LEN/128), 256>>>(x, wq, qb, qp, T_LEN, QCOLS, D_DIM);
    gemm_bias_kernel<<<dim3(KCOLS/128, T_LEN/128), 256>>>(x, wk, kb, kp, T_LEN, KCOLS, D_DIM);
    gemm_bias_kernel<<<dim3(KCOLS/128, T_LEN/128), 256>>>(x, wv, vb, vp, T_LEN, KCOLS, D_DIM);

    // RoPE
    rope_kernel<<<(T_LEN * NHEADS * 64 + 255) / 256, 256>>>(qp, sinp, cosp, NHEADS);
    rope_kernel<<<(T_LEN * KVH    * 64 + 255) / 256, 256>>>(kp, sinp, cosp, KVH);

    // Flash attention
    flash_kernel<<<dim3(T_LEN/64, NHEADS), 256, FLASH_SMEM>>>();

    // Output projection -> d_out
    gemm_bias_kernel<<<dim3(D_DIM/128, T_LEN/128), 256>>>(aop, wo, nullptr, out, T_LEN, D_DIM, QCOLS);
}

// round 6
// speedup vs baseline: 4.4163x; 4.4163x over previous
#include <cuda_runtime.h>
#include <cstddef>
#include <cstdint>

#define T_LEN   2048
#define D_DIM   3584
#define NHEADS  28
#define KVH     4
#define HD      128
#define GRP     7
#define QCOLS   (NHEADS*HD)   // 3584
#define KCOLS   (KVH*HD)      // 512
#define SCALE_ATTN 0.08838834764831845f

// -------- scratch (no cudaMalloc allowed) --------
__device__ float g_q [T_LEN * NHEADS * HD];
__device__ float g_k [T_LEN * KVH    * HD];
__device__ float g_v [T_LEN * KVH    * HD];
__device__ float g_ao[T_LEN * NHEADS * HD];

// ---------------- helpers ----------------
__device__ __forceinline__ unsigned tf32u(float x) {
    unsigned u; asm("cvt.rna.tf32.f32 %0, %1;" : "=r"(u) : "f"(x)); return u;
}
__device__ __forceinline__ float tf32f(float x) { return __uint_as_float(tf32u(x)); }

__device__ __forceinline__ void mma8(float* c, unsigned a0, unsigned a1, unsigned a2,
                                     unsigned a3, unsigned b0, unsigned b1) {
    asm volatile(
        "mma.sync.aligned.m16n8k8.row.col.f32.tf32.tf32.f32 "
        "{%0,%1,%2,%3}, {%4,%5,%6,%7}, {%8,%9}, {%0,%1,%2,%3};"
        : "+f"(c[0]), "+f"(c[1]), "+f"(c[2]), "+f"(c[3])
        : "r"(a0), "r"(a1), "r"(a2), "r"(a3), "r"(b0), "r"(b1));
}

__device__ __forceinline__ void cpasync16(float* dst_smem, const float* src) {
    unsigned s = (unsigned)__cvta_generic_to_shared(dst_smem);
    asm volatile("cp.async.cg.shared.global [%0], [%1], 16;" :: "r"(s), "l"(src));
}

// =====================================================================
// tf32 tensor-core GEMM: C[M x Ncols] = A[M x K] * B[K x Ncols] (+bias)
// BM=128, BN=128, BK=32, 256 thr (8 warps, warp tile 64x32).
// cp.async double-buffered smem.  M%128==0, Ncols%128==0, K%32==0.
// =====================================================================
#define BKG   32
#define ASTR  40     // As [m][k], stride 40 -> frag banks 8g+t (conflict-free)
#define BSTR  136    // Bs [k][n], stride 136 -> frag banks 8t+g
#define GBUF  (128*ASTR + BKG*BSTR)          // floats per stage: 5120+4352=9472
#define GEMM_SMEM (GBUF * 2 * 4)             // 75776 bytes

__global__ __launch_bounds__(256, 2)
void gemm_tc(const float* __restrict__ A, const float* __restrict__ B,
             const float* __restrict__ bias, float* __restrict__ C,
             int M, int Ncols, int K)
{
    extern __shared__ float smg[];
    const int tid = threadIdx.x;
    const int lane = tid & 31, group = lane >> 2, tig = lane & 3;
    const int w = tid >> 5, wm = w >> 2, wn = w & 3;   // warp grid 2x4
    const int brow = blockIdx.x * 128, bcol = blockIdx.y * 128;

    float acc[4][4][4];
#pragma unroll
    for (int mt = 0; mt < 4; mt++)
#pragma unroll
        for (int nt = 0; nt < 4; nt++)
#pragma unroll
            for (int r = 0; r < 4; r++) acc[mt][nt][r] = 0.f;

    const int nIter = K / BKG;

    // issue cp.async for K-tile starting at k0 into stage b
    auto issue = [&](int k0, int b) {
        float* as = smg + b * GBUF;
        float* bs = as + 128 * ASTR;
#pragma unroll
        for (int i = 0; i < 4; i++) {
            int f = tid + i * 256;            // 0..1023 float4 slots (A: 128x32)
            int m = f >> 3, kq = (f & 7) * 4;
            cpasync16(as + m * ASTR + kq, A + (size_t)(brow + m) * K + k0 + kq);
        }
#pragma unroll
        for (int i = 0; i < 4; i++) {
            int f = tid + i * 256;            // B: 32x128
            int kr = f >> 5, n4 = (f & 31) * 4;
            cpasync16(bs + kr * BSTR + n4, B + (size_t)(k0 + kr) * Ncols + bcol + n4);
        }
        asm volatile("cp.async.commit_group;");
    };

    issue(0, 0);

    for (int it = 0; it < nIter; ++it) {
        asm volatile("cp.async.wait_group 0;" ::: "memory");
        __syncthreads();
        if (it + 1 < nIter) issue((it + 1) * BKG, (it + 1) & 1);

        const float* as = smg + (it & 1) * GBUF;
        const float* bs = as + 128 * ASTR;

#pragma unroll
        for (int ks = 0; ks < 4; ks++) {
            const int kb = ks * 8;
            unsigned a[4][4];
#pragma unroll
            for (int mt = 0; mt < 4; mt++) {
                const float* p0 = as + (wm * 64 + mt * 16 + group) * ASTR + kb + tig;
                const float* p1 = p0 + 8 * ASTR;
                a[mt][0] = tf32u(p0[0]);
                a[mt][1] = tf32u(p1[0]);
                a[mt][2] = tf32u(p0[4]);
                a[mt][3] = tf32u(p1[4]);
            }
#pragma unroll
            for (int nt = 0; nt < 4; nt++) {
                const float* q0 = bs + (kb + tig) * BSTR + wn * 32 + nt * 8 + group;
                unsigned b0 = tf32u(q0[0]);
                unsigned b1 = tf32u(q0[4 * BSTR]);
#pragma unroll
                for (int mt = 0; mt < 4; mt++)
                    mma8(acc[mt][nt], a[mt][0], a[mt][1], a[mt][2], a[mt][3], b0, b1);
            }
        }
    }

    // epilogue
#pragma unroll
    for (int mt = 0; mt < 4; mt++) {
        int row0 = brow + wm * 64 + mt * 16 + group;
#pragma unroll
        for (int nt = 0; nt < 4; nt++) {
            int col = bcol + wn * 32 + nt * 8 + 2 * tig;
            float b0 = bias ? bias[col] : 0.f;
            float b1 = bias ? bias[col + 1] : 0.f;
            float2 v0 = make_float2(acc[mt][nt][0] + b0, acc[mt][nt][1] + b1);
            float2 v1 = make_float2(acc[mt][nt][2] + b0, acc[mt][nt][3] + b1);
            *(float2*)(C + (size_t)row0 * Ncols + col)       = v0;
            *(float2*)(C + (size_t)(row0 + 8) * Ncols + col) = v1;
        }
    }
}

// =====================================================================
// RoPE (unchanged): layout (t, heads, 128); pair (h, h+64)
// =====================================================================
__global__ __launch_bounds__(256)
void rope_kernel(float* __restrict__ q, const float* __restrict__ sinp,
                 const float* __restrict__ cosp, int heads)
{
    int idx = blockIdx.x * blockDim.x + threadIdx.x;
    int total = T_LEN * heads * 64;
    if (idx >= total) return;
    int h = idx & 63;
    int tmp = idx >> 6;
    int n = tmp % heads;
    int t = tmp / heads;
    float s = sinp[t * 64 + h];
    float c = cosp[t * 64 + h];
    float* p = q + ((size_t)t * heads + n) * HD + h;
    float x1 = p[0], x2 = p[64];
    p[0]  = x1 * c - x2 * s;
    p[64] = x2 * c + x1 * s;
}

// =====================================================================
// Tensor-core flash attention.  BM=128 q-rows, BN=64 keys/tile.
// 8 warps; warp w owns q-rows 16w..16w+15 (full 64-col S strip, full
// 128-col O strip).  mma tf32 for S and PV; online softmax via shfl
// within 4-lane groups; P goes through smem (tf32).
// grid = (T/128, NHEADS)
// =====================================================================
#define QSTR 136
#define KSTR 136
#define VSTR 136
#define PSTR 72
#define FLASH_SMEM ((128*QSTR + 64*KSTR + 64*VSTR + 128*PSTR) * 4)  // 176128

__global__ __launch_bounds__(256, 1)
void flash_tc_kernel()
{
    extern __shared__ float sm[];
    float* Qs = sm;                        // [128][136] tf32 (pre-scaled)
    float* Ks = Qs + 128 * QSTR;           // [64][136]  tf32
    float* Vs = Ks + 64 * KSTR;            // [64][136]  tf32
    float* Ps = Vs + 64 * VSTR;            // [128][72]  tf32

    const int br = blockIdx.x;             // q row-block (128 rows)
    const int n  = blockIdx.y;
    const int kh = n / GRP;
    const int tid = threadIdx.x;
    const int lane = tid & 31, group = lane >> 2, tig = lane & 3;
    const int w = tid >> 5;
    const int rowbase = w * 16;

    // ---- load Q tile: scale + tf32 ----
    {
        const float* Qg = g_q + (size_t)(br * 128) * QCOLS + n * HD;
#pragma unroll
        for (int i = 0; i < 16; i++) {
            int f = tid + i * 256;               // 0..4095 float4 slots
            int r = f >> 5, c4 = (f & 31) << 2;
            float4 v = *(const float4*)(Qg + (size_t)r * QCOLS + c4);
            float* d = Qs + r * QSTR + c4;
            d[0] = tf32f(v.x * SCALE_ATTN);
            d[1] = tf32f(v.y * SCALE_ATTN);
            d[2] = tf32f(v.z * SCALE_ATTN);
            d[3] = tf32f(v.w * SCALE_ATTN);
        }
    }

    float m0 = -1e30f, m1 = -1e30f, l0 = 0.f, l1 = 0.f;
    float acc[16][4];
#pragma unroll
    for (int nt = 0; nt < 16; nt++)
#pragma unroll
        for (int r = 0; r < 4; r++) acc[nt][r] = 0.f;

    const float* q0 = Qs + (rowbase + group) * QSTR;
    const float* q1 = q0 + 8 * QSTR;
    float* p0 = Ps + (rowbase + group) * PSTR;
    float* p1 = p0 + 8 * PSTR;

    const int jmax = 2 * br + 1;
    for (int j = 0; j <= jmax; ++j) {
        // K tile -> regs (overlaps barrier wait)
        const float* Kg = g_k + (size_t)(j * 64) * KCOLS + kh * HD;
        const float* Vg = g_v + (size_t)(j * 64) * KCOLS + kh * HD;
        float4 kreg[8];
#pragma unroll
        for (int i = 0; i < 8; i++) {
            int f = tid + i * 256;               // 0..2047
            int r = f >> 5, c4 = (f & 31) << 2;
            kreg[i] = *(const float4*)(Kg + (size_t)r * KCOLS + c4);
        }
        __syncthreads();    // all warps done with Ks/Vs of previous tile
#pragma unroll
        for (int i = 0; i < 8; i++) {
            int f = tid + i * 256;
            int r = f >> 5, c4 = (f & 31) << 2;
            float* d = Ks + r * KSTR + c4;
            d[0] = tf32f(kreg[i].x); d[1] = tf32f(kreg[i].y);
            d[2] = tf32f(kreg[i].z); d[3] = tf32f(kreg[i].w);
        }
#pragma unroll
        for (int i = 0; i < 8; i++) {
            int f = tid + i * 256;
            int r = f >> 5, c4 = (f & 31) << 2;
            float4 v = *(const float4*)(Vg + (size_t)r * KCOLS + c4);
            float* d = Vs + r * VSTR + c4;
            d[0] = tf32f(v.x); d[1] = tf32f(v.y);
            d[2] = tf32f(v.z); d[3] = tf32f(v.w);
        }
        __syncthreads();

        // ---- S = Q K^T (warp: 16 rows x 64 cols) ----
        float s_acc[8][4];
#pragma unroll
        for (int nt = 0; nt < 8; nt++)
#pragma unroll
            for (int r = 0; r < 4; r++) s_acc[nt][r] = 0.f;

#pragma unroll
        for (int kk = 0; kk < 16; kk++) {
            int k = kk * 8 + tig;
            unsigned a0 = __float_as_uint(q0[k]);
            unsigned a1 = __float_as_uint(q1[k]);
            unsigned a2 = __float_as_uint(q0[k + 4]);
            unsigned a3 = __float_as_uint(q1[k + 4]);
#pragma unroll
            for (int nt = 0; nt < 8; nt++) {
                const float* kr = Ks + (nt * 8 + group) * KSTR + k;
                unsigned b0 = __float_as_uint(kr[0]);
                unsigned b1 = __float_as_uint(kr[4]);
                mma8(s_acc[nt], a0, a1, a2, a3, b0, b1);
            }
        }

        // ---- causal mask (only boundary tiles) ----
        if (j >= 2 * br) {
            int q0r = br * 128 + rowbase + group;
            int q1r = q0r + 8;
            int kb0 = j * 64;
#pragma unroll
            for (int nt = 0; nt < 8; nt++) {
                int c0 = kb0 + nt * 8 + 2 * tig, c1 = c0 + 1;
                if (c0 > q0r) s_acc[nt][0] = -1e30f;
                if (c1 > q0r) s_acc[nt][1] = -1e30f;
                if (c0 > q1r) s_acc[nt][2] = -1e30f;
                if (c1 > q1r) s_acc[nt][3] = -1e30f;
            }
        }

        // ---- online softmax ----
        float rmax0 = -1e30f, rmax1 = -1e30f;
#pragma unroll
        for (int nt = 0; nt < 8; nt++) {
            rmax0 = fmaxf(rmax0, fmaxf(s_acc[nt][0], s_acc[nt][1]));
            rmax1 = fmaxf(rmax1, fmaxf(s_acc[nt][2], s_acc[nt][3]));
        }
        rmax0 = fmaxf(rmax0, __shfl_xor_sync(0xffffffffu, rmax0, 1));
        rmax0 = fmaxf(rmax0, __shfl_xor_sync(0xffffffffu, rmax0, 2));
        rmax1 = fmaxf(rmax1, __shfl_xor_sync(0xffffffffu, rmax1, 1));
        rmax1 = fmaxf(rmax1, __shfl_xor_sync(0xffffffffu, rmax1, 2));
        float mn0 = fmaxf(m0, rmax0), mn1 = fmaxf(m1, rmax1);
        float alpha0 = __expf(m0 - mn0), alpha1 = __expf(m1 - mn1);
        float sum0 = 0.f, sum1 = 0.f;
#pragma unroll
        for (int nt = 0; nt < 8; nt++) {
            float e0 = __expf(s_acc[nt][0] - mn0);
            float e1 = __expf(s_acc[nt][1] - mn0);
            float e2 = __expf(s_acc[nt][2] - mn1);
            float e3 = __expf(s_acc[nt][3] - mn1);
            sum0 += e0 + e1;  sum1 += e2 + e3;
            *(float2*)(p0 + nt * 8 + 2 * tig) = make_float2(tf32f(e0), tf32f(e1));
            *(float2*)(p1 + nt * 8 + 2 * tig) = make_float2(tf32f(e2), tf32f(e3));
        }
        sum0 += __shfl_xor_sync(0xffffffffu, sum0, 1);
        sum0 += __shfl_xor_sync(0xffffffffu, sum0, 2);
        sum1 += __shfl_xor_sync(0xffffffffu, sum1, 1);
        sum1 += __shfl_xor_sync(0xffffffffu, sum1, 2);
        l0 = l0 * alpha0 + sum0;  m0 = mn0;
        l1 = l1 * alpha1 + sum1;  m1 = mn1;
#pragma unroll
        for (int nt = 0; nt < 16; nt++) {
            acc[nt][0] *= alpha0;  acc[nt][1] *= alpha0;
            acc[nt][2] *= alpha1;  acc[nt][3] *= alpha1;
        }
        __syncwarp();   // P smem visible warp-wide (rows are warp-private)

        // ---- O += P V (warp: 16 rows x 128 cols) ----
#pragma unroll
        for (int kk = 0; kk < 8; kk++) {
            int s = kk * 8 + tig;
            unsigned a0 = __float_as_uint(p0[s]);
            unsigned a1 = __float_as_uint(p1[s]);
            unsigned a2 = __float_as_uint(p0[s + 4]);
            unsigned a3 = __float_as_uint(p1[s + 4]);
            const float* v0r = Vs + s * VSTR;
            const float* v4r = v0r + 4 * VSTR;
#pragma unroll
            for (int nt = 0; nt < 16; nt++) {
                unsigned b0 = __float_as_uint(v0r[nt * 8 + group]);
                unsigned b1 = __float_as_uint(v4r[nt * 8 + group]);
                mma8(acc[nt], a0, a1, a2, a3, b0, b1);
            }
        }
    }

    // ---- epilogue ----
    float rl0 = 1.f / l0, rl1 = 1.f / l1;
    int row0 = br * 128 + rowbase + group;
    float* op0 = g_ao + (size_t)row0 * QCOLS + n * HD;
    float* op1 = op0 + (size_t)8 * QCOLS;
#pragma unroll
    for (int nt = 0; nt < 16; nt++) {
        int col = nt * 8 + 2 * tig;
        *(float2*)(op0 + col) = make_float2(acc[nt][0] * rl0, acc[nt][1] * rl0);
        *(float2*)(op1 + col) = make_float2(acc[nt][2] * rl1, acc[nt][3] * rl1);
    }
}

// =====================================================================
extern "C" void kernel_launch(void* const* d_in, const int* in_sizes, int n_in,
                              void* d_out, int out_size)
{
    const float* x    = (const float*)d_in[0];
    const float* sinp = (const float*)d_in[2];
    const float* cosp = (const float*)d_in[3];
    const float* wq   = (const float*)d_in[4];
    const float* wk   = (const float*)d_in[5];
    const float* wv   = (const float*)d_in[6];
    const float* wo   = (const float*)d_in[7];
    const float* qb   = (const float*)d_in[8];
    const float* kb   = (const float*)d_in[9];
    const float* vb   = (const float*)d_in[10];
    float* out = (float*)d_out;

    float *qp, *kp, *vp, *aop;
    cudaGetSymbolAddress((void**)&qp,  g_q);
    cudaGetSymbolAddress((void**)&kp,  g_k);
    cudaGetSymbolAddress((void**)&vp,  g_v);
    cudaGetSymbolAddress((void**)&aop, g_ao);

    cudaFuncSetAttribute(gemm_tc,
                         cudaFuncAttributeMaxDynamicSharedMemorySize, GEMM_SMEM);
    cudaFuncSetAttribute(flash_tc_kernel,
                         cudaFuncAttributeMaxDynamicSharedMemorySize, FLASH_SMEM);

    // QKV projections (+bias).  grid.x = row-blocks (B-strip reuse in L2)
    gemm_tc<<<dim3(T_LEN/128, QCOLS/128), 256, GEMM_SMEM>>>(x, wq, qb, qp, T_LEN, QCOLS, D_DIM);
    gemm_tc<<<dim3(T_LEN/128, KCOLS/128), 256, GEMM_SMEM>>>(x, wk, kb, kp, T_LEN, KCOLS, D_DIM);
    gemm_tc<<<dim3(T_LEN/128, KCOLS/128), 256, GEMM_SMEM>>>(x, wv, vb, vp, T_LEN, KCOLS, D_DIM);

    // RoPE
    rope_kernel<<<(T_LEN * NHEADS * 64 + 255) / 256, 256>>>(qp, sinp, cosp, NHEADS);
    rope_kernel<<<(T_LEN * KVH    * 64 + 255) / 256, 256>>>(kp, sinp, cosp, KVH);

    // Flash attention (tensor cores)
    flash_tc_kernel<<<dim3(T_LEN/128, NHEADS), 256, FLASH_SMEM>>>();

    // Output projection -> d_out
    gemm_tc<<<dim3(T_LEN/128, D_DIM/128), 256, GEMM_SMEM>>>(aop, wo, nullptr, out, T_LEN, D_DIM, QCOLS);
}

// round 9
// speedup vs baseline: 7.8071x; 1.7678x over previous
#include <cuda_runtime.h>
#include <cuda_fp16.h>
#include <cstddef>
#include <cstdint>

#define T_LEN   2048
#define D_DIM   3584
#define NHEADS  28
#define KVH     4
#define HD      128
#define GRP     7
#define QCOLS   (NHEADS*HD)   // 3584
#define KCOLS   (KVH*HD)      // 512
#define SCALE_ATTN 0.08838834764831845f

// -------- scratch (no cudaMalloc allowed) --------
__device__ float  g_q  [T_LEN * QCOLS];          // Q proj fp32 (pre-rope)
__device__ float  g_k  [T_LEN * KCOLS];
__device__ float  g_v  [T_LEN * KCOLS];
__device__ __half g_xh [T_LEN * D_DIM];          // x fp16
__device__ __half g_wqT[QCOLS * D_DIM];          // W^T fp16 [N][K]
__device__ __half g_wkT[KCOLS * D_DIM];
__device__ __half g_wvT[KCOLS * D_DIM];
__device__ __half g_woT[D_DIM * QCOLS];
__device__ __half g_qh [T_LEN * QCOLS];          // rope(Q)*scale fp16
__device__ __half g_kh [T_LEN * KCOLS];          // rope(K) fp16
__device__ __half g_vh [T_LEN * KCOLS];          // V fp16
__device__ __half g_aoh[T_LEN * QCOLS];          // attention out fp16

// ---------------- helpers ----------------
__device__ __forceinline__ void cpa16(uint32_t dst, const void* src) {
    asm volatile("cp.async.cg.shared.global [%0], [%1], 16;" :: "r"(dst), "l"(src));
}
__device__ __forceinline__ void ldm4(uint32_t* r, uint32_t a) {
    asm volatile("ldmatrix.sync.aligned.m8n8.x4.shared.b16 {%0,%1,%2,%3}, [%4];"
                 : "=r"(r[0]), "=r"(r[1]), "=r"(r[2]), "=r"(r[3]) : "r"(a));
}
__device__ __forceinline__ void ldm4t(uint32_t* r, uint32_t a) {
    asm volatile("ldmatrix.sync.aligned.m8n8.x4.trans.shared.b16 {%0,%1,%2,%3}, [%4];"
                 : "=r"(r[0]), "=r"(r[1]), "=r"(r[2]), "=r"(r[3]) : "r"(a));
}
__device__ __forceinline__ void mma16(float* c, const uint32_t* a, uint32_t b0, uint32_t b1) {
    asm volatile(
        "mma.sync.aligned.m16n8k16.row.col.f32.f16.f16.f32 "
        "{%0,%1,%2,%3}, {%4,%5,%6,%7}, {%8,%9}, {%0,%1,%2,%3};"
        : "+f"(c[0]), "+f"(c[1]), "+f"(c[2]), "+f"(c[3])
        : "r"(a[0]), "r"(a[1]), "r"(a[2]), "r"(a[3]), "r"(b0), "r"(b1));
}
__device__ __forceinline__ uint32_t h2u(float a, float b) {
    __half2 h = __floats2half2_rn(a, b);
    return *reinterpret_cast<uint32_t*>(&h);
}

// =====================================================================
// prepass: fp32 -> fp16 convert, and transpose+convert for weights
// =====================================================================
__global__ __launch_bounds__(256)
void cvt_h_kernel(const float* __restrict__ s, __half* __restrict__ d, int n4)
{
    int i = blockIdx.x * blockDim.x + threadIdx.x;
    if (i >= n4) return;
    float4 v = ((const float4*)s)[i];
    ((__half2*)d)[2*i]   = __floats2half2_rn(v.x, v.y);
    ((__half2*)d)[2*i+1] = __floats2half2_rn(v.z, v.w);
}

// src[rows][cols] fp32  ->  dst[cols][rows] fp16 ; rows,cols % 32 == 0
__global__ __launch_bounds__(256)
void transpose_h_kernel(const float* __restrict__ src, __half* __restrict__ dst,
                        int rows, int cols)
{
    __shared__ float tile[32][33];
    int bx = blockIdx.x * 32;   // col base
    int by = blockIdx.y * 32;   // row base
    int tx = threadIdx.x & 31, ty = threadIdx.x >> 5;
#pragma unroll
    for (int i = 0; i < 4; i++)
        tile[ty + i*8][tx] = src[(size_t)(by + ty + i*8) * cols + bx + tx];
    __syncthreads();
#pragma unroll
    for (int i = 0; i < 4; i++)
        dst[(size_t)(bx + ty + i*8) * rows + by + tx] = __float2half(tile[tx][ty + i*8]);
}

// =====================================================================
// fp16 tensor-core GEMM: C[M x Ncols] = A[M x K] * BT[Ncols x K]^T (+bias)
// CTA 128x128, BK=32, 256 thr (8 warps 2x4, warp tile 64x32), cp.async x2.
// =====================================================================
#define GSTGH 10240                          // halfs per stage (A 5120 + B 5120)
#define GEMM_SMEM (2 * GSTGH * 2)            // 40960 bytes

__global__ __launch_bounds__(256, 2)
void gemm_h(const __half* __restrict__ A, const __half* __restrict__ BT,
            const float* __restrict__ bias, float* __restrict__ C,
            int Ncols, int K)
{
    extern __shared__ __half smh[];
    const uint32_t sbase = (uint32_t)__cvta_generic_to_shared(smh);
    const int tid = threadIdx.x, lane = tid & 31;
    const int w = tid >> 5, wm = w >> 2, wn = w & 3;
    const int brow = blockIdx.x * 128, bcol = blockIdx.y * 128;
    const int nIter = K / 32;

    float acc[4][4][4];
#pragma unroll
    for (int mt = 0; mt < 4; mt++)
#pragma unroll
        for (int nt = 0; nt < 4; nt++)
#pragma unroll
            for (int r = 0; r < 4; r++) acc[mt][nt][r] = 0.f;

    auto issue = [&](int k0, int s) {
        uint32_t ab = sbase + (uint32_t)(s * GSTGH * 2);
        uint32_t bb = ab + 5120 * 2;
#pragma unroll
        for (int i = 0; i < 2; i++) {
            int f = tid + i * 256;          // 0..511
            int m = f >> 2, c = (f & 3) * 8;
            cpa16(ab + (uint32_t)(m * 40 + c) * 2, A + (size_t)(brow + m) * K + k0 + c);
        }
#pragma unroll
        for (int i = 0; i < 2; i++) {
            int f = tid + i * 256;
            int nr = f >> 2, c = (f & 3) * 8;
            cpa16(bb + (uint32_t)(nr * 40 + c) * 2, BT + (size_t)(bcol + nr) * K + k0 + c);
        }
        asm volatile("cp.async.commit_group;");
    };

    issue(0, 0);

    for (int it = 0; it < nIter; ++it) {
        if (it + 1 < nIter) {
            issue((it + 1) * 32, (it + 1) & 1);
            asm volatile("cp.async.wait_group 1;" ::: "memory");
        } else {
            asm volatile("cp.async.wait_group 0;" ::: "memory");
        }
        __syncthreads();
        uint32_t ab = sbase + (uint32_t)((it & 1) * GSTGH * 2);
        uint32_t bb = ab + 5120 * 2;

#pragma unroll
        for (int ks = 0; ks < 2; ks++) {
            const int koff = ks * 16 + (lane >> 4) * 8;
            uint32_t a[4][4], b[2][4];
#pragma unroll
            for (int mt = 0; mt < 4; mt++)
                ldm4(a[mt], ab + (uint32_t)((wm*64 + mt*16 + (lane & 15)) * 40 + koff) * 2);
#pragma unroll
            for (int nb = 0; nb < 2; nb++)
                ldm4(b[nb], bb + (uint32_t)((wn*32 + nb*16 + (lane & 15)) * 40 + koff) * 2);
#pragma unroll
            for (int mt = 0; mt < 4; mt++)
#pragma unroll
                for (int nb = 0; nb < 2; nb++) {
                    mma16(acc[mt][nb*2+0], a[mt], b[nb][0], b[nb][2]);
                    mma16(acc[mt][nb*2+1], a[mt], b[nb][1], b[nb][3]);
                }
        }
        __syncthreads();
    }

    // epilogue
    const int g = lane >> 2, t2 = (lane & 3) * 2;
#pragma unroll
    for (int mt = 0; mt < 4; mt++) {
        int row0 = brow + wm*64 + mt*16 + g;
#pragma unroll
        for (int nt = 0; nt < 4; nt++) {
            int col = bcol + wn*32 + nt*8 + t2;
            float b0 = bias ? bias[col] : 0.f;
            float b1 = bias ? bias[col + 1] : 0.f;
            *(float2*)(C + (size_t)row0 * Ncols + col) =
                make_float2(acc[mt][nt][0] + b0, acc[mt][nt][1] + b1);
            *(float2*)(C + (size_t)(row0 + 8) * Ncols + col) =
                make_float2(acc[mt][nt][2] + b0, acc[mt][nt][3] + b1);
        }
    }
}

// =====================================================================
// RoPE -> fp16 (scale folded for Q): layout (t, heads, 128), pair (h, h+64)
// =====================================================================
__global__ __launch_bounds__(256)
void rope_h_kernel(const float* __restrict__ src, __half* __restrict__ dst,
                   const float* __restrict__ sinp, const float* __restrict__ cosp,
                   int heads, float scale)
{
    int idx = blockIdx.x * blockDim.x + threadIdx.x;
    int total = T_LEN * heads * 64;
    if (idx >= total) return;
    int h = idx & 63;
    int tmp = idx >> 6;
    int n = tmp % heads;
    int t = tmp / heads;
    float s = sinp[t * 64 + h];
    float c = cosp[t * 64 + h];
    size_t p = ((size_t)t * heads + n) * HD + h;
    float x1 = src[p], x2 = src[p + 64];
    dst[p]      = __float2half((x1 * c - x2 * s) * scale);
    dst[p + 64] = __float2half((x2 * c + x1 * s) * scale);
}

// =====================================================================
// fp16 flash attention.  BM=128, BN=64, 8 warps (warp = 16 q-rows).
// Q in registers across the loop; P stays in registers (S frag == PV A frag);
// K via ldmatrix, V via ldmatrix.trans; K/V cp.async double-buffered.
// grid = (T/128, NHEADS)
// =====================================================================
#define QBYTES  (128 * 136 * 2)     // 34816
#define KVSTG   (2 * 64 * 136 * 2)  // K + V per stage = 34816
#define FLASH_SMEM (QBYTES + 2 * KVSTG)   // 104448

__global__ __launch_bounds__(256, 1)
void flash_h_kernel()
{
    extern __shared__ __half smf[];
    const uint32_t sbase = (uint32_t)__cvta_generic_to_shared(smf);
    const int br = blockIdx.x, n = blockIdx.y, kh = n / GRP;
    const int tid = threadIdx.x, lane = tid & 31;
    const int g = lane >> 2, t2 = (lane & 3) * 2;
    const int w = tid >> 5, rowbase = w * 16;

    auto issue_kv = [&](int j, int s) {
        const __half* Kg = g_kh + (size_t)(j * 64) * KCOLS + kh * HD;
        const __half* Vg = g_vh + (size_t)(j * 64) * KCOLS + kh * HD;
        uint32_t Kb = sbase + QBYTES + (uint32_t)(s * KVSTG);
        uint32_t Vb = Kb + 64 * 136 * 2;
#pragma unroll
        for (int i = 0; i < 4; i++) {
            int f = tid + i * 256;           // 0..1023
            int r = f >> 4, c = (f & 15) * 8;
            cpa16(Kb + (uint32_t)(r * 136 + c) * 2, Kg + (size_t)r * KCOLS + c);
        }
#pragma unroll
        for (int i = 0; i < 4; i++) {
            int f = tid + i * 256;
            int r = f >> 4, c = (f & 15) * 8;
            cpa16(Vb + (uint32_t)(r * 136 + c) * 2, Vg + (size_t)r * KCOLS + c);
        }
        asm volatile("cp.async.commit_group;");
    };

    // ---- Q tile cp.async (group 0), then KV tile 0 (group 1) ----
    {
        const __half* Qg = g_qh + (size_t)(br * 128) * QCOLS + n * HD;
#pragma unroll
        for (int i = 0; i < 8; i++) {
            int f = tid + i * 256;           // 0..2047
            int r = f >> 4, c = (f & 15) * 8;
            cpa16(sbase + (uint32_t)(r * 136 + c) * 2, Qg + (size_t)r * QCOLS + c);
        }
        asm volatile("cp.async.commit_group;");
    }
    issue_kv(0, 0);
    asm volatile("cp.async.wait_group 1;" ::: "memory");   // Q done
    __syncthreads();

    // ---- Q fragments to registers ----
    uint32_t qf[8][4];
#pragma unroll
    for (int kk = 0; kk < 8; kk++)
        ldm4(qf[kk], sbase + (uint32_t)((rowbase + (lane & 15)) * 136
                                        + kk * 16 + (lane >> 4) * 8) * 2);

    float m0 = -1e30f, m1 = -1e30f, l0 = 0.f, l1 = 0.f;
    float acc[16][4];
#pragma unroll
    for (int nt = 0; nt < 16; nt++)
#pragma unroll
        for (int r = 0; r < 4; r++) acc[nt][r] = 0.f;

    const int jmax = 2 * br + 1;
    for (int j = 0; j <= jmax; ++j) {
        const int s = j & 1;
        if (j < jmax) {
            issue_kv(j + 1, s ^ 1);
            asm volatile("cp.async.wait_group 1;" ::: "memory");
        } else {
            asm volatile("cp.async.wait_group 0;" ::: "memory");
        }
        __syncthreads();
        uint32_t Kb = sbase + QBYTES + (uint32_t)(s * KVSTG);
        uint32_t Vb = Kb + 64 * 136 * 2;

        // ---- S = Q K^T ----
        float s_acc[8][4];
#pragma unroll
        for (int nt = 0; nt < 8; nt++)
#pragma unroll
            for (int r = 0; r < 4; r++) s_acc[nt][r] = 0.f;

#pragma unroll
        for (int kk = 0; kk < 8; kk++) {
            const int koff = kk * 16 + (lane >> 4) * 8;
#pragma unroll
            for (int nb = 0; nb < 4; nb++) {
                uint32_t bk[4];
                ldm4(bk, Kb + (uint32_t)((nb*16 + (lane & 15)) * 136 + koff) * 2);
                mma16(s_acc[nb*2+0], qf[kk], bk[0], bk[2]);
                mma16(s_acc[nb*2+1], qf[kk], bk[1], bk[3]);
            }
        }

        // ---- causal mask (boundary tiles only) ----
        if (j >= 2 * br) {
            int q0r = br * 128 + rowbase + g;
            int q1r = q0r + 8;
            int kb0 = j * 64;
#pragma unroll
            for (int nt = 0; nt < 8; nt++) {
                int c0 = kb0 + nt * 8 + t2, c1 = c0 + 1;
                if (c0 > q0r) s_acc[nt][0] = -1e30f;
                if (c1 > q0r) s_acc[nt][1] = -1e30f;
                if (c0 > q1r) s_acc[nt][2] = -1e30f;
                if (c1 > q1r) s_acc[nt][3] = -1e30f;
            }
        }

        // ---- online softmax ----
        float rmax0 = -1e30f, rmax1 = -1e30f;
#pragma unroll
        for (int nt = 0; nt < 8; nt++) {
            rmax0 = fmaxf(rmax0, fmaxf(s_acc[nt][0], s_acc[nt][1]));
            rmax1 = fmaxf(rmax1, fmaxf(s_acc[nt][2], s_acc[nt][3]));
        }
        rmax0 = fmaxf(rmax0, __shfl_xor_sync(0xffffffffu, rmax0, 1));
        rmax0 = fmaxf(rmax0, __shfl_xor_sync(0xffffffffu, rmax0, 2));
        rmax1 = fmaxf(rmax1, __shfl_xor_sync(0xffffffffu, rmax1, 1));
        rmax1 = fmaxf(rmax1, __shfl_xor_sync(0xffffffffu, rmax1, 2));
        float mn0 = fmaxf(m0, rmax0), mn1 = fmaxf(m1, rmax1);
        float alpha0 = __expf(m0 - mn0), alpha1 = __expf(m1 - mn1);

        uint32_t pa[4][4];     // PV A-fragments (P in registers)
        float sum0 = 0.f, sum1 = 0.f;
#pragma unroll
        for (int nt = 0; nt < 8; nt++) {
            float e0 = __expf(s_acc[nt][0] - mn0);
            float e1 = __expf(s_acc[nt][1] - mn0);
            float e2 = __expf(s_acc[nt][2] - mn1);
            float e3 = __expf(s_acc[nt][3] - mn1);
            sum0 += e0 + e1;  sum1 += e2 + e3;
            const int kk2 = nt >> 1, hi = (nt & 1) * 2;
            pa[kk2][hi + 0] = h2u(e0, e1);
            pa[kk2][hi + 1] = h2u(e2, e3);
        }
        sum0 += __shfl_xor_sync(0xffffffffu, sum0, 1);
        sum0 += __shfl_xor_sync(0xffffffffu, sum0, 2);
        sum1 += __shfl_xor_sync(0xffffffffu, sum1, 1);
        sum1 += __shfl_xor_sync(0xffffffffu, sum1, 2);
        l0 = l0 * alpha0 + sum0;  m0 = mn0;
        l1 = l1 * alpha1 + sum1;  m1 = mn1;
#pragma unroll
        for (int nt = 0; nt < 16; nt++) {
            acc[nt][0] *= alpha0;  acc[nt][1] *= alpha0;
            acc[nt][2] *= alpha1;  acc[nt][3] *= alpha1;
        }

        // ---- O += P V  (V via ldmatrix.trans) ----
#pragma unroll
        for (int kk2 = 0; kk2 < 4; kk2++) {
            const int srow = kk2 * 16 + ((lane >> 3) & 1) * 8 + (lane & 7);
            const int dofb = (lane >> 4) * 8;
#pragma unroll
            for (int db = 0; db < 8; db++) {
                uint32_t bv[4];
                ldm4t(bv, Vb + (uint32_t)(srow * 136 + db * 16 + dofb) * 2);
                mma16(acc[db*2+0], pa[kk2], bv[0], bv[1]);
                mma16(acc[db*2+1], pa[kk2], bv[2], bv[3]);
            }
        }
        __syncthreads();   // stage s free for re-issue
    }

    // ---- epilogue: fp16 to g_aoh (A operand of O-projection) ----
    float rl0 = 1.f / l0, rl1 = 1.f / l1;
    int row0 = br * 128 + rowbase + g;
    __half* op0 = g_aoh + (size_t)row0 * QCOLS + n * HD;
    __half* op1 = op0 + (size_t)8 * QCOLS;
#pragma unroll
    for (int nt = 0; nt < 16; nt++) {
        int col = nt * 8 + t2;
        *(__half2*)(op0 + col) = __floats2half2_rn(acc[nt][0] * rl0, acc[nt][1] * rl0);
        *(__half2*)(op1 + col) = __floats2half2_rn(acc[nt][2] * rl1, acc[nt][3] * rl1);
    }
}

// =====================================================================
extern "C" void kernel_launch(void* const* d_in, const int* in_sizes, int n_in,
                              void* d_out, int out_size)
{
    const float* x    = (const float*)d_in[0];
    const float* sinp = (const float*)d_in[2];
    const float* cosp = (const float*)d_in[3];
    const float* wq   = (const float*)d_in[4];
    const float* wk   = (const float*)d_in[5];
    const float* wv   = (const float*)d_in[6];
    const float* wo   = (const float*)d_in[7];
    const float* qb   = (const float*)d_in[8];
    const float* kb   = (const float*)d_in[9];
    const float* vb   = (const float*)d_in[10];
    float* out = (float*)d_out;

    float *qp, *kp, *vp;
    __half *xh, *wqT, *wkT, *wvT, *woT, *qh, *kkh, *vh, *aoh;
    cudaGetSymbolAddress((void**)&qp,  g_q);
    cudaGetSymbolAddress((void**)&kp,  g_k);
    cudaGetSymbolAddress((void**)&vp,  g_v);
    cudaGetSymbolAddress((void**)&xh,  g_xh);
    cudaGetSymbolAddress((void**)&wqT, g_wqT);
    cudaGetSymbolAddress((void**)&wkT, g_wkT);
    cudaGetSymbolAddress((void**)&wvT, g_wvT);
    cudaGetSymbolAddress((void**)&woT, g_woT);
    cudaGetSymbolAddress((void**)&qh,  g_qh);
    cudaGetSymbolAddress((void**)&kkh, g_kh);
    cudaGetSymbolAddress((void**)&vh,  g_vh);
    cudaGetSymbolAddress((void**)&aoh, g_aoh);

    cudaFuncSetAttribute(gemm_h,
                         cudaFuncAttributeMaxDynamicSharedMemorySize, GEMM_SMEM);
    cudaFuncSetAttribute(flash_h_kernel,
                         cudaFuncAttributeMaxDynamicSharedMemorySize, FLASH_SMEM);

    // ---- prepass: fp16 conversion + weight transposes ----
    cvt_h_kernel<<<(T_LEN*D_DIM/4 + 255)/256, 256>>>(x, xh, T_LEN*D_DIM/4);
    transpose_h_kernel<<<dim3(QCOLS/32, D_DIM/32), 256>>>(wq, wqT, D_DIM, QCOLS);
    transpose_h_kernel<<<dim3(KCOLS/32, D_DIM/32), 256>>>(wk, wkT, D_DIM, KCOLS);
    transpose_h_kernel<<<dim3(KCOLS/32, D_DIM/32), 256>>>(wv, wvT, D_DIM, KCOLS);
    transpose_h_kernel<<<dim3(D_DIM/32, QCOLS/32), 256>>>(wo, woT, QCOLS, D_DIM);

    // ---- QKV projections (+bias), fp32 outputs ----
    gemm_h<<<dim3(T_LEN/128, QCOLS/128), 256, GEMM_SMEM>>>(xh, wqT, qb, qp, QCOLS, D_DIM);
    gemm_h<<<dim3(T_LEN/128, KCOLS/128), 256, GEMM_SMEM>>>(xh, wkT, kb, kp, KCOLS, D_DIM);
    gemm_h<<<dim3(T_LEN/128, KCOLS/128), 256, GEMM_SMEM>>>(xh, wvT, vb, vp, KCOLS, D_DIM);

    // ---- RoPE -> fp16 (Q pre-scaled), V -> fp16 ----
    rope_h_kernel<<<(T_LEN*NHEADS*64 + 255)/256, 256>>>(qp, qh, sinp, cosp, NHEADS, SCALE_ATTN);
    rope_h_kernel<<<(T_LEN*KVH*64 + 255)/256, 256>>>(kp, kkh, sinp, cosp, KVH, 1.0f);
    cvt_h_kernel<<<(T_LEN*KCOLS/4 + 255)/256, 256>>>(vp, vh, T_LEN*KCOLS/4);

    // ---- flash attention ----
    flash_h_kernel<<<dim3(T_LEN/128, NHEADS), 256, FLASH_SMEM>>>();

    // ---- output projection -> d_out ----
    gemm_h<<<dim3(T_LEN/128, D_DIM/128), 256, GEMM_SMEM>>>(aoh, woT, nullptr, out, D_DIM, QCOLS);
}

// round 11
// speedup vs baseline: 8.9782x; 1.1500x over previous
#include <cuda_runtime.h>
#include <cuda_fp16.h>
#include <cstddef>
#include <cstdint>

#define T_LEN   2048
#define D_DIM   3584
#define NHEADS  28
#define KVH     4
#define HD      128
#define GRP     7
#define QCOLS   (NHEADS*HD)   // 3584
#define KCOLS   (KVH*HD)      // 512
#define QKVCOLS (QCOLS + 2*KCOLS)  // 4608
#define SCALE_ATTN 0.08838834764831845f

// -------- scratch (no cudaMalloc allowed) --------
__device__ float  g_q  [T_LEN * QCOLS];          // Q proj fp32 (pre-rope)
__device__ float  g_k  [T_LEN * KCOLS];          // K proj fp32 (pre-rope)
__device__ __half g_xh [T_LEN * D_DIM];          // x fp16
__device__ __half g_wqkvT[QKVCOLS * D_DIM];      // [wq;wk;wv]^T fp16 [4608][3584]
__device__ __half g_woT[D_DIM * QCOLS];
__device__ __half g_qh [T_LEN * QCOLS];          // rope(Q)*scale fp16
__device__ __half g_kh [T_LEN * KCOLS];          // rope(K) fp16
__device__ __half g_vh [T_LEN * KCOLS];          // V fp16 (written by fused GEMM)
__device__ __half g_aoh[T_LEN * QCOLS];          // attention out fp16

// ---------------- helpers ----------------
__device__ __forceinline__ void cpa16(uint32_t dst, const void* src) {
    asm volatile("cp.async.cg.shared.global [%0], [%1], 16;" :: "r"(dst), "l"(src));
}
__device__ __forceinline__ void ldm4(uint32_t* r, uint32_t a) {
    asm volatile("ldmatrix.sync.aligned.m8n8.x4.shared.b16 {%0,%1,%2,%3}, [%4];"
                 : "=r"(r[0]), "=r"(r[1]), "=r"(r[2]), "=r"(r[3]) : "r"(a));
}
__device__ __forceinline__ void ldm4t(uint32_t* r, uint32_t a) {
    asm volatile("ldmatrix.sync.aligned.m8n8.x4.trans.shared.b16 {%0,%1,%2,%3}, [%4];"
                 : "=r"(r[0]), "=r"(r[1]), "=r"(r[2]), "=r"(r[3]) : "r"(a));
}
__device__ __forceinline__ void mma16(float* c, const uint32_t* a, uint32_t b0, uint32_t b1) {
    asm volatile(
        "mma.sync.aligned.m16n8k16.row.col.f32.f16.f16.f32 "
        "{%0,%1,%2,%3}, {%4,%5,%6,%7}, {%8,%9}, {%0,%1,%2,%3};"
        : "+f"(c[0]), "+f"(c[1]), "+f"(c[2]), "+f"(c[3])
        : "r"(a[0]), "r"(a[1]), "r"(a[2]), "r"(a[3]), "r"(b0), "r"(b1));
}
__device__ __forceinline__ uint32_t h2u(float a, float b) {
    __half2 h = __floats2half2_rn(a, b);
    return *reinterpret_cast<uint32_t*>(&h);
}

// =====================================================================
// prepass
// =====================================================================
__global__ __launch_bounds__(256)
void cvt_h_kernel(const float* __restrict__ s, __half* __restrict__ d, int n4)
{
    int i = blockIdx.x * blockDim.x + threadIdx.x;
    if (i >= n4) return;
    float4 v = ((const float4*)s)[i];
    ((__half2*)d)[2*i]   = __floats2half2_rn(v.x, v.y);
    ((__half2*)d)[2*i+1] = __floats2half2_rn(v.z, v.w);
}

// src[rows][cols] fp32  ->  dst[cols][rows] fp16 ; rows,cols % 32 == 0
__global__ __launch_bounds__(256)
void transpose_h_kernel(const float* __restrict__ src, __half* __restrict__ dst,
                        int rows, int cols)
{
    __shared__ float tile[32][33];
    int bx = blockIdx.x * 32;
    int by = blockIdx.y * 32;
    int tx = threadIdx.x & 31, ty = threadIdx.x >> 5;
#pragma unroll
    for (int i = 0; i < 4; i++)
        tile[ty + i*8][tx] = src[(size_t)(by + ty + i*8) * cols + bx + tx];
    __syncthreads();
#pragma unroll
    for (int i = 0; i < 4; i++)
        dst[(size_t)(bx + ty + i*8) * rows + by + tx] = __float2half(tile[tx][ty + i*8]);
}

// =====================================================================
// shared GEMM mainloop: CTA 128x128, BK=32, 3-stage cp.async, 256 thr,
// 8 warps 2x4, warp tile 64x32.  Accumulators acc[4][4][4].
// =====================================================================
#define GSTGB 20480                       // bytes per stage (A 10240 + B 10240)
#define GEMM_SMEM (3 * GSTGB)             // 61440

struct GemmCtx {
    uint32_t sbase;
    int tid, lane, wm, wn;
    int brow, bcol;
};

__device__ __forceinline__ void gemm_mainloop(
    const GemmCtx& cx, const __half* __restrict__ A, const __half* __restrict__ BT,
    int K, float acc[4][4][4])
{
#pragma unroll
    for (int mt = 0; mt < 4; mt++)
#pragma unroll
        for (int nt = 0; nt < 4; nt++)
#pragma unroll
            for (int r = 0; r < 4; r++) acc[mt][nt][r] = 0.f;

    const int nIter = K / 32;
    const int tid = cx.tid, lane = cx.lane;

    auto issue = [&](int it, int s) {
        const int k0 = it * 32;
        uint32_t ab = cx.sbase + (uint32_t)(s * GSTGB);
        uint32_t bb = ab + 10240;
#pragma unroll
        for (int i = 0; i < 2; i++) {
            int f = tid + i * 256;
            int m = f >> 2, c = (f & 3) * 8;
            cpa16(ab + (uint32_t)(m * 40 + c) * 2, A + (size_t)(cx.brow + m) * K + k0 + c);
        }
#pragma unroll
        for (int i = 0; i < 2; i++) {
            int f = tid + i * 256;
            int nr = f >> 2, c = (f & 3) * 8;
            cpa16(bb + (uint32_t)(nr * 40 + c) * 2, BT + (size_t)(cx.bcol + nr) * K + k0 + c);
        }
        asm volatile("cp.async.commit_group;");
    };

    issue(0, 0);
    issue(1, 1);

    for (int it = 0; it < nIter; ++it) {
        if (it < nIter - 1) asm volatile("cp.async.wait_group 1;" ::: "memory");
        else                asm volatile("cp.async.wait_group 0;" ::: "memory");
        __syncthreads();
        if (it + 2 < nIter) issue(it + 2, (it + 2) % 3);

        uint32_t ab = cx.sbase + (uint32_t)((it % 3) * GSTGB);
        uint32_t bb = ab + 10240;
#pragma unroll
        for (int ks = 0; ks < 2; ks++) {
            const int koff = ks * 16 + (lane >> 4) * 8;
            uint32_t a[4][4], b[2][4];
#pragma unroll
            for (int mt = 0; mt < 4; mt++)
                ldm4(a[mt], ab + (uint32_t)((cx.wm*64 + mt*16 + (lane & 15)) * 40 + koff) * 2);
#pragma unroll
            for (int nb = 0; nb < 2; nb++)
                ldm4(b[nb], bb + (uint32_t)((cx.wn*32 + nb*16 + (lane & 15)) * 40 + koff) * 2);
#pragma unroll
            for (int mt = 0; mt < 4; mt++)
#pragma unroll
                for (int nb = 0; nb < 2; nb++) {
                    mma16(acc[mt][nb*2+0], a[mt], b[nb][0], b[nb][2]);
                    mma16(acc[mt][nb*2+1], a[mt], b[nb][1], b[nb][3]);
                }
        }
    }
}

// ---- fused QKV projection: BT = [wq;wk;wv]^T, routes output by blockIdx.y ----
__global__ __launch_bounds__(256, 2)
void gemm_qkv(const __half* __restrict__ A, const __half* __restrict__ BT,
              const float* __restrict__ qb, const float* __restrict__ kb,
              const float* __restrict__ vb)
{
    extern __shared__ __half smh[];
    GemmCtx cx;
    cx.sbase = (uint32_t)__cvta_generic_to_shared(smh);
    cx.tid = threadIdx.x; cx.lane = cx.tid & 31;
    int w = cx.tid >> 5; cx.wm = w >> 2; cx.wn = w & 3;
    cx.brow = blockIdx.x * 128; cx.bcol = blockIdx.y * 128;

    float acc[4][4][4];
    gemm_mainloop(cx, A, BT, D_DIM, acc);

    const int g = cx.lane >> 2, t2 = (cx.lane & 3) * 2;
    const int by = blockIdx.y;

    if (by < 28) {          // ---- Q -> g_q fp32 ----
        const int cb = cx.bcol;
#pragma unroll
        for (int mt = 0; mt < 4; mt++) {
            int row0 = cx.brow + cx.wm*64 + mt*16 + g;
#pragma unroll
            for (int nt = 0; nt < 4; nt++) {
                int col = cb + cx.wn*32 + nt*8 + t2;
                float b0 = qb[col], b1 = qb[col + 1];
                *(float2*)(g_q + (size_t)row0 * QCOLS + col) =
                    make_float2(acc[mt][nt][0] + b0, acc[mt][nt][1] + b1);
                *(float2*)(g_q + (size_t)(row0 + 8) * QCOLS + col) =
                    make_float2(acc[mt][nt][2] + b0, acc[mt][nt][3] + b1);
            }
        }
    } else if (by < 32) {   // ---- K -> g_k fp32 ----
        const int cb = cx.bcol - QCOLS;
#pragma unroll
        for (int mt = 0; mt < 4; mt++) {
            int row0 = cx.brow + cx.wm*64 + mt*16 + g;
#pragma unroll
            for (int nt = 0; nt < 4; nt++) {
                int col = cb + cx.wn*32 + nt*8 + t2;
                float b0 = kb[col], b1 = kb[col + 1];
                *(float2*)(g_k + (size_t)row0 * KCOLS + col) =
                    make_float2(acc[mt][nt][0] + b0, acc[mt][nt][1] + b1);
                *(float2*)(g_k + (size_t)(row0 + 8) * KCOLS + col) =
                    make_float2(acc[mt][nt][2] + b0, acc[mt][nt][3] + b1);
            }
        }
    } else {                // ---- V -> g_vh fp16 (fp32 acc+bias, then rn) ----
        const int cb = cx.bcol - QCOLS - KCOLS;
#pragma unroll
        for (int mt = 0; mt < 4; mt++) {
            int row0 = cx.brow + cx.wm*64 + mt*16 + g;
#pragma unroll
            for (int nt = 0; nt < 4; nt++) {
                int col = cb + cx.wn*32 + nt*8 + t2;
                float b0 = vb[col], b1 = vb[col + 1];
                *(__half2*)(g_vh + (size_t)row0 * KCOLS + col) =
                    __floats2half2_rn(acc[mt][nt][0] + b0, acc[mt][nt][1] + b1);
                *(__half2*)(g_vh + (size_t)(row0 + 8) * KCOLS + col) =
                    __floats2half2_rn(acc[mt][nt][2] + b0, acc[mt][nt][3] + b1);
            }
        }
    }
}

// ---- generic GEMM (O-projection): fp32 out, no bias ----
__global__ __launch_bounds__(256, 2)
void gemm_h(const __half* __restrict__ A, const __half* __restrict__ BT,
            float* __restrict__ C, int Ncols, int K)
{
    extern __shared__ __half smh[];
    GemmCtx cx;
    cx.sbase = (uint32_t)__cvta_generic_to_shared(smh);
    cx.tid = threadIdx.x; cx.lane = cx.tid & 31;
    int w = cx.tid >> 5; cx.wm = w >> 2; cx.wn = w & 3;
    cx.brow = blockIdx.x * 128; cx.bcol = blockIdx.y * 128;

    float acc[4][4][4];
    gemm_mainloop(cx, A, BT, K, acc);

    const int g = cx.lane >> 2, t2 = (cx.lane & 3) * 2;
#pragma unroll
    for (int mt = 0; mt < 4; mt++) {
        int row0 = cx.brow + cx.wm*64 + mt*16 + g;
#pragma unroll
        for (int nt = 0; nt < 4; nt++) {
            int col = cx.bcol + cx.wn*32 + nt*8 + t2;
            *(float2*)(C + (size_t)row0 * Ncols + col) =
                make_float2(acc[mt][nt][0], acc[mt][nt][1]);
            *(float2*)(C + (size_t)(row0 + 8) * Ncols + col) =
                make_float2(acc[mt][nt][2], acc[mt][nt][3]);
        }
    }
}

// =====================================================================
// RoPE -> fp16 (scale folded for Q): layout (t, heads, 128), pair (h, h+64)
// =====================================================================
__global__ __launch_bounds__(256)
void rope_h_kernel(const float* __restrict__ src, __half* __restrict__ dst,
                   const float* __restrict__ sinp, const float* __restrict__ cosp,
                   int heads, float scale)
{
    int idx = blockIdx.x * blockDim.x + threadIdx.x;
    int total = T_LEN * heads * 64;
    if (idx >= total) return;
    int h = idx & 63;
    int tmp = idx >> 6;
    int n = tmp % heads;
    int t = tmp / heads;
    float s = sinp[t * 64 + h];
    float c = cosp[t * 64 + h];
    size_t p = ((size_t)t * heads + n) * HD + h;
    float x1 = src[p], x2 = src[p + 64];
    dst[p]      = __float2half((x1 * c - x2 * s) * scale);
    dst[p + 64] = __float2half((x2 * c + x1 * s) * scale);
}

// =====================================================================
// fp16 flash attention.  BM=128, BN=64, 8 warps; Q + P in registers;
// K ldmatrix, V ldmatrix.trans; K/V 3-stage cp.async, 1 sync per tile.
// grid = (T/128, NHEADS)
// =====================================================================
#define QBYTES  (128 * 136 * 2)     // 34816
#define KVSTG   (2 * 64 * 136 * 2)  // 34816
#define FLASH_SMEM (QBYTES + 3 * KVSTG)   // 139264

__global__ __launch_bounds__(256, 1)
void flash_h_kernel()
{
    extern __shared__ __half smf[];
    const uint32_t sbase = (uint32_t)__cvta_generic_to_shared(smf);
    const int br = blockIdx.x, n = blockIdx.y, kh = n / GRP;
    const int tid = threadIdx.x, lane = tid & 31;
    const int g = lane >> 2, t2 = (lane & 3) * 2;
    const int w = tid >> 5, rowbase = w * 16;

    auto issue_kv = [&](int j, int s) {
        const __half* Kg = g_kh + (size_t)(j * 64) * KCOLS + kh * HD;
        const __half* Vg = g_vh + (size_t)(j * 64) * KCOLS + kh * HD;
        uint32_t Kb = sbase + QBYTES + (uint32_t)(s * KVSTG);
        uint32_t Vb = Kb + 64 * 136 * 2;
#pragma unroll
        for (int i = 0; i < 4; i++) {
            int f = tid + i * 256;
            int r = f >> 4, c = (f & 15) * 8;
            cpa16(Kb + (uint32_t)(r * 136 + c) * 2, Kg + (size_t)r * KCOLS + c);
        }
#pragma unroll
        for (int i = 0; i < 4; i++) {
            int f = tid + i * 256;
            int r = f >> 4, c = (f & 15) * 8;
            cpa16(Vb + (uint32_t)(r * 136 + c) * 2, Vg + (size_t)r * KCOLS + c);
        }
        asm volatile("cp.async.commit_group;");
    };

    const int jmax = 2 * br + 1;

    // ---- prologue: Q + first two KV tiles ----
    {
        const __half* Qg = g_qh + (size_t)(br * 128) * QCOLS + n * HD;
#pragma unroll
        for (int i = 0; i < 8; i++) {
            int f = tid + i * 256;
            int r = f >> 4, c = (f & 15) * 8;
            cpa16(sbase + (uint32_t)(r * 136 + c) * 2, Qg + (size_t)r * QCOLS + c);
        }
        asm volatile("cp.async.commit_group;");
    }
    issue_kv(0, 0);
    issue_kv(1, 1);
    asm volatile("cp.async.wait_group 2;" ::: "memory");   // Q done
    __syncthreads();

    uint32_t qf[8][4];
#pragma unroll
    for (int kk = 0; kk < 8; kk++)
        ldm4(qf[kk], sbase + (uint32_t)((rowbase + (lane & 15)) * 136
                                        + kk * 16 + (lane >> 4) * 8) * 2);

    float m0 = -1e30f, m1 = -1e30f, l0 = 0.f, l1 = 0.f;
    float acc[16][4];
#pragma unroll
    for (int nt = 0; nt < 16; nt++)
#pragma unroll
        for (int r = 0; r < 4; r++) acc[nt][r] = 0.f;

    for (int j = 0; j <= jmax; ++j) {
        if (j < jmax) asm volatile("cp.async.wait_group 1;" ::: "memory");
        else          asm volatile("cp.async.wait_group 0;" ::: "memory");
        __syncthreads();
        if (j + 2 <= jmax) issue_kv(j + 2, (j + 2) % 3);

        uint32_t Kb = sbase + QBYTES + (uint32_t)((j % 3) * KVSTG);
        uint32_t Vb = Kb + 64 * 136 * 2;

        // ---- S = Q K^T ----
        float s_acc[8][4];
#pragma unroll
        for (int nt = 0; nt < 8; nt++)
#pragma unroll
            for (int r = 0; r < 4; r++) s_acc[nt][r] = 0.f;

#pragma unroll
        for (int kk = 0; kk < 8; kk++) {
            const int koff = kk * 16 + (lane >> 4) * 8;
#pragma unroll
            for (int nb = 0; nb < 4; nb++) {
                uint32_t bk[4];
                ldm4(bk, Kb + (uint32_t)((nb*16 + (lane & 15)) * 136 + koff) * 2);
                mma16(s_acc[nb*2+0], qf[kk], bk[0], bk[2]);
                mma16(s_acc[nb*2+1], qf[kk], bk[1], bk[3]);
            }
        }

        // ---- causal mask (boundary tiles only) ----
        if (j >= 2 * br) {
            int q0r = br * 128 + rowbase + g;
            int q1r = q0r + 8;
            int kb0 = j * 64;
#pragma unroll
            for (int nt = 0; nt < 8; nt++) {
                int c0 = kb0 + nt * 8 + t2, c1 = c0 + 1;
                if (c0 > q0r) s_acc[nt][0] = -1e30f;
                if (c1 > q0r) s_acc[nt][1] = -1e30f;
                if (c0 > q1r) s_acc[nt][2] = -1e30f;
                if (c1 > q1r) s_acc[nt][3] = -1e30f;
            }
        }

        // ---- online softmax ----
        float rmax0 = -1e30f, rmax1 = -1e30f;
#pragma unroll
        for (int nt = 0; nt < 8; nt++) {
            rmax0 = fmaxf(rmax0, fmaxf(s_acc[nt][0], s_acc[nt][1]));
            rmax1 = fmaxf(rmax1, fmaxf(s_acc[nt][2], s_acc[nt][3]));
        }
        rmax0 = fmaxf(rmax0, __shfl_xor_sync(0xffffffffu, rmax0, 1));
        rmax0 = fmaxf(rmax0, __shfl_xor_sync(0xffffffffu, rmax0, 2));
        rmax1 = fmaxf(rmax1, __shfl_xor_sync(0xffffffffu, rmax1, 1));
        rmax1 = fmaxf(rmax1, __shfl_xor_sync(0xffffffffu, rmax1, 2));
        float mn0 = fmaxf(m0, rmax0), mn1 = fmaxf(m1, rmax1);
        float alpha0 = __expf(m0 - mn0), alpha1 = __expf(m1 - mn1);

        uint32_t pa[4][4];
        float sum0 = 0.f, sum1 = 0.f;
#pragma unroll
        for (int nt = 0; nt < 8; nt++) {
            float e0 = __expf(s_acc[nt][0] - mn0);
            float e1 = __expf(s_acc[nt][1] - mn0);
            float e2 = __expf(s_acc[nt][2] - mn1);
            float e3 = __expf(s_acc[nt][3] - mn1);
            sum0 += e0 + e1;  sum1 += e2 + e3;
            const int kk2 = nt >> 1, hi = (nt & 1) * 2;
            pa[kk2][hi + 0] = h2u(e0, e1);
            pa[kk2][hi + 1] = h2u(e2, e3);
        }
        sum0 += __shfl_xor_sync(0xffffffffu, sum0, 1);
        sum0 += __shfl_xor_sync(0xffffffffu, sum0, 2);
        sum1 += __shfl_xor_sync(0xffffffffu, sum1, 1);
        sum1 += __shfl_xor_sync(0xffffffffu, sum1, 2);
        l0 = l0 * alpha0 + sum0;  m0 = mn0;
        l1 = l1 * alpha1 + sum1;  m1 = mn1;
#pragma unroll
        for (int nt = 0; nt < 16; nt++) {
            acc[nt][0] *= alpha0;  acc[nt][1] *= alpha0;
            acc[nt][2] *= alpha1;  acc[nt][3] *= alpha1;
        }

        // ---- O += P V  (V via ldmatrix.trans) ----
#pragma unroll
        for (int kk2 = 0; kk2 < 4; kk2++) {
            const int srow = kk2 * 16 + ((lane >> 3) & 1) * 8 + (lane & 7);
            const int dofb = (lane >> 4) * 8;
#pragma unroll
            for (int db = 0; db < 8; db++) {
                uint32_t bv[4];
                ldm4t(bv, Vb + (uint32_t)(srow * 136 + db * 16 + dofb) * 2);
                mma16(acc[db*2+0], pa[kk2], bv[0], bv[1]);
                mma16(acc[db*2+1], pa[kk2], bv[2], bv[3]);
            }
        }
    }

    // ---- epilogue: fp16 to g_aoh ----
    float rl0 = 1.f / l0, rl1 = 1.f / l1;
    int row0 = br * 128 + rowbase + g;
    __half* op0 = g_aoh + (size_t)row0 * QCOLS + n * HD;
    __half* op1 = op0 + (size_t)8 * QCOLS;
#pragma unroll
    for (int nt = 0; nt < 16; nt++) {
        int col = nt * 8 + t2;
        *(__half2*)(op0 + col) = __floats2half2_rn(acc[nt][0] * rl0, acc[nt][1] * rl0);
        *(__half2*)(op1 + col) = __floats2half2_rn(acc[nt][2] * rl1, acc[nt][3] * rl1);
    }
}

// =====================================================================
extern "C" void kernel_launch(void* const* d_in, const int* in_sizes, int n_in,
                              void* d_out, int out_size)
{
    const float* x    = (const float*)d_in[0];
    const float* sinp = (const float*)d_in[2];
    const float* cosp = (const float*)d_in[3];
    const float* wq   = (const float*)d_in[4];
    const float* wk   = (const float*)d_in[5];
    const float* wv   = (const float*)d_in[6];
    const float* wo   = (const float*)d_in[7];
    const float* qb   = (const float*)d_in[8];
    const float* kb   = (const float*)d_in[9];
    const float* vb   = (const float*)d_in[10];
    float* out = (float*)d_out;

    float *qp, *kp;
    __half *xh, *wqkvT, *woT, *qh, *kkh, *aoh;
    cudaGetSymbolAddress((void**)&qp,    g_q);
    cudaGetSymbolAddress((void**)&kp,    g_k);
    cudaGetSymbolAddress((void**)&xh,    g_xh);
    cudaGetSymbolAddress((void**)&wqkvT, g_wqkvT);
    cudaGetSymbolAddress((void**)&woT,   g_woT);
    cudaGetSymbolAddress((void**)&qh,    g_qh);
    cudaGetSymbolAddress((void**)&kkh,   g_kh);
    cudaGetSymbolAddress((void**)&aoh,   g_aoh);

    cudaFuncSetAttribute(gemm_qkv,
                         cudaFuncAttributeMaxDynamicSharedMemorySize, GEMM_SMEM);
    cudaFuncSetAttribute(gemm_h,
                         cudaFuncAttributeMaxDynamicSharedMemorySize, GEMM_SMEM);
    cudaFuncSetAttribute(flash_h_kernel,
                         cudaFuncAttributeMaxDynamicSharedMemorySize, FLASH_SMEM);

    // ---- prepass: fp16 x + transposed weights (wq|wk|wv concatenated) ----
    cvt_h_kernel<<<(T_LEN*D_DIM/4 + 255)/256, 256>>>(x, xh, T_LEN*D_DIM/4);
    transpose_h_kernel<<<dim3(QCOLS/32, D_DIM/32), 256>>>(wq, wqkvT, D_DIM, QCOLS);
    transpose_h_kernel<<<dim3(KCOLS/32, D_DIM/32), 256>>>(wk, wqkvT + (size_t)QCOLS*D_DIM, D_DIM, KCOLS);
    transpose_h_kernel<<<dim3(KCOLS/32, D_DIM/32), 256>>>(wv, wqkvT + (size_t)(QCOLS+KCOLS)*D_DIM, D_DIM, KCOLS);
    transpose_h_kernel<<<dim3(D_DIM/32, QCOLS/32), 256>>>(wo, woT, QCOLS, D_DIM);

    // ---- fused QKV projection (V written fp16 directly) ----
    gemm_qkv<<<dim3(T_LEN/128, QKVCOLS/128), 256, GEMM_SMEM>>>(xh, wqkvT, qb, kb, vb);

    // ---- RoPE -> fp16 (Q pre-scaled) ----
    rope_h_kernel<<<(T_LEN*NHEADS*64 + 255)/256, 256>>>(qp, qh, sinp, cosp, NHEADS, SCALE_ATTN);
    rope_h_kernel<<<(T_LEN*KVH*64 + 255)/256, 256>>>(kp, kkh, sinp, cosp, KVH, 1.0f);

    // ---- flash attention ----
    flash_h_kernel<<<dim3(T_LEN/128, NHEADS), 256, FLASH_SMEM>>>();

    // ---- output projection -> d_out ----
    gemm_h<<<dim3(T_LEN/128, D_DIM/128), 256, GEMM_SMEM>>>(aoh, woT, out, D_DIM, QCOLS);
}

// round 12
// speedup vs baseline: 10.8544x; 1.2090x over previous
#include <cuda_runtime.h>
#include <cuda_fp16.h>
#include <cstddef>
#include <cstdint>

#define T_LEN   2048
#define D_DIM   3584
#define NHEADS  28
#define KVH     4
#define HD      128
#define GRP     7
#define QCOLS   (NHEADS*HD)   // 3584
#define KCOLS   (KVH*HD)      // 512
#define SCALE_ATTN 0.08838834764831845f

// -------- scratch (no cudaMalloc allowed) --------
__device__ float  g_q  [T_LEN * QCOLS];          // Q proj fp32 (pre-rope)
__device__ float  g_k  [T_LEN * KCOLS];          // K proj fp32 (pre-rope)
__device__ __half g_xh [T_LEN * D_DIM];          // x fp16
__device__ __half g_wqh[D_DIM * QCOLS];          // wq fp16 (K-major, natural layout)
__device__ __half g_wkh[D_DIM * KCOLS];
__device__ __half g_wvh[D_DIM * KCOLS];
__device__ __half g_woh[QCOLS * D_DIM];          // wo fp16 [nh][d] (natural layout)
__device__ __half g_qh [T_LEN * QCOLS];          // rope(Q)*scale fp16
__device__ __half g_kh [T_LEN * KCOLS];          // rope(K) fp16
__device__ __half g_vh [T_LEN * KCOLS];          // V fp16 (written by fused GEMM)
__device__ __half g_aoh[T_LEN * QCOLS];          // attention out fp16

// ---------------- helpers ----------------
__device__ __forceinline__ void cpa16(uint32_t dst, const void* src) {
    asm volatile("cp.async.cg.shared.global [%0], [%1], 16;" :: "r"(dst), "l"(src));
}
__device__ __forceinline__ void ldm4(uint32_t* r, uint32_t a) {
    asm volatile("ldmatrix.sync.aligned.m8n8.x4.shared.b16 {%0,%1,%2,%3}, [%4];"
                 : "=r"(r[0]), "=r"(r[1]), "=r"(r[2]), "=r"(r[3]) : "r"(a));
}
__device__ __forceinline__ void ldm4t(uint32_t* r, uint32_t a) {
    asm volatile("ldmatrix.sync.aligned.m8n8.x4.trans.shared.b16 {%0,%1,%2,%3}, [%4];"
                 : "=r"(r[0]), "=r"(r[1]), "=r"(r[2]), "=r"(r[3]) : "r"(a));
}
__device__ __forceinline__ void mma16(float* c, const uint32_t* a, uint32_t b0, uint32_t b1) {
    asm volatile(
        "mma.sync.aligned.m16n8k16.row.col.f32.f16.f16.f32 "
        "{%0,%1,%2,%3}, {%4,%5,%6,%7}, {%8,%9}, {%0,%1,%2,%3};"
        : "+f"(c[0]), "+f"(c[1]), "+f"(c[2]), "+f"(c[3])
        : "r"(a[0]), "r"(a[1]), "r"(a[2]), "r"(a[3]), "r"(b0), "r"(b1));
}
__device__ __forceinline__ uint32_t h2u(float a, float b) {
    __half2 h = __floats2half2_rn(a, b);
    return *reinterpret_cast<uint32_t*>(&h);
}

// =====================================================================
// prepass: fp32 -> fp16 (no transposes needed anymore)
// =====================================================================
__global__ __launch_bounds__(256)
void cvt_h_kernel(const float* __restrict__ s, __half* __restrict__ d, int n4)
{
    int i = blockIdx.x * blockDim.x + threadIdx.x;
    if (i >= n4) return;
    float4 v = ((const float4*)s)[i];
    ((__half2*)d)[2*i]   = __floats2half2_rn(v.x, v.y);
    ((__half2*)d)[2*i+1] = __floats2half2_rn(v.z, v.w);
}

// =====================================================================
// GEMM mainloop: CTA 128x128, BK=32, 3-stage cp.async, 128 threads,
// 4 warps (2x2), warp tile 64x64.  B stored K-major [k][n], consumed via
// ldmatrix.trans (same addressing pattern as flash V — proven).
// =====================================================================
#define ABYT 10240                        // A: 128 rows x 40 halfs x 2B
#define GSTGB (ABYT + 32*136*2)           // + B: 32 rows x 136 halfs -> 18944
#define GEMM_SMEM (3 * GSTGB)             // 56832

__device__ __forceinline__ void gemm_mainloop(
    uint32_t sbase, int tid, int lane, int wm, int wn, int brow, int bcol,
    const __half* __restrict__ A, const __half* __restrict__ B,
    int Ncols, int K, float acc[4][8][4])
{
#pragma unroll
    for (int mt = 0; mt < 4; mt++)
#pragma unroll
        for (int nt = 0; nt < 8; nt++)
#pragma unroll
            for (int r = 0; r < 4; r++) acc[mt][nt][r] = 0.f;

    const int nIter = K / 32;

    auto issue = [&](int it, int s) {
        const int k0 = it * 32;
        uint32_t ab = sbase + (uint32_t)(s * GSTGB);
        uint32_t bb = ab + ABYT;
#pragma unroll
        for (int i = 0; i < 4; i++) {
            int f = tid + i * 128;             // 0..511
            int m = f >> 2, c = (f & 3) * 8;
            cpa16(ab + (uint32_t)(m * 40 + c) * 2, A + (size_t)(brow + m) * K + k0 + c);
        }
#pragma unroll
        for (int i = 0; i < 4; i++) {
            int f = tid + i * 128;             // 0..511
            int kr = f >> 4, nc = (f & 15) * 8;
            cpa16(bb + (uint32_t)(kr * 136 + nc) * 2, B + (size_t)(k0 + kr) * Ncols + bcol + nc);
        }
        asm volatile("cp.async.commit_group;");
    };

    issue(0, 0);
    issue(1, 1);

    const int dofb = (lane >> 4) * 8;
    const int srb  = ((lane >> 3) & 1) * 8 + (lane & 7);

    for (int it = 0; it < nIter; ++it) {
        if (it < nIter - 1) asm volatile("cp.async.wait_group 1;" ::: "memory");
        else                asm volatile("cp.async.wait_group 0;" ::: "memory");
        __syncthreads();
        if (it + 2 < nIter) issue(it + 2, (it + 2) % 3);

        uint32_t ab = sbase + (uint32_t)((it % 3) * GSTGB);
        uint32_t bb = ab + ABYT;
#pragma unroll
        for (int ks = 0; ks < 2; ks++) {
            const int koff = ks * 16;
            uint32_t a[4][4];
#pragma unroll
            for (int mt = 0; mt < 4; mt++)
                ldm4(a[mt], ab + (uint32_t)((wm*64 + mt*16 + (lane & 15)) * 40
                                            + koff + dofb) * 2);
#pragma unroll
            for (int db = 0; db < 4; db++) {
                uint32_t bv[4];
                ldm4t(bv, bb + (uint32_t)((koff + srb) * 136
                                          + wn*64 + db*16 + dofb) * 2);
#pragma unroll
                for (int mt = 0; mt < 4; mt++) {
                    mma16(acc[mt][db*2+0], a[mt], bv[0], bv[1]);
                    mma16(acc[mt][db*2+1], a[mt], bv[2], bv[3]);
                }
            }
        }
    }
}

// ---- fused QKV projection: picks weight/bias by blockIdx.y ----
__global__ __launch_bounds__(128, 2)
void gemm_qkv(const __half* __restrict__ A,
              const float* __restrict__ qb, const float* __restrict__ kb,
              const float* __restrict__ vb)
{
    extern __shared__ __half smh[];
    const uint32_t sbase = (uint32_t)__cvta_generic_to_shared(smh);
    const int tid = threadIdx.x, lane = tid & 31;
    const int w = tid >> 5, wm = w >> 1, wn = w & 1;
    const int brow = blockIdx.x * 128;
    const int by = blockIdx.y;

    const __half* B;
    int bcol, Ncols, mode;
    if (by < 28)      { B = g_wqh; bcol = by * 128;        Ncols = QCOLS; mode = 0; }
    else if (by < 32) { B = g_wkh; bcol = (by - 28) * 128; Ncols = KCOLS; mode = 1; }
    else              { B = g_wvh; bcol = (by - 32) * 128; Ncols = KCOLS; mode = 2; }

    float acc[4][8][4];
    gemm_mainloop(sbase, tid, lane, wm, wn, brow, bcol, A, B, Ncols, D_DIM, acc);

    const int g = lane >> 2, t2 = (lane & 3) * 2;

    if (mode == 0) {        // Q -> g_q fp32
#pragma unroll
        for (int mt = 0; mt < 4; mt++) {
            int row0 = brow + wm*64 + mt*16 + g;
#pragma unroll
            for (int nt = 0; nt < 8; nt++) {
                int col = bcol + wn*64 + nt*8 + t2;
                float b0 = qb[col], b1 = qb[col + 1];
                *(float2*)(g_q + (size_t)row0 * QCOLS + col) =
                    make_float2(acc[mt][nt][0] + b0, acc[mt][nt][1] + b1);
                *(float2*)(g_q + (size_t)(row0 + 8) * QCOLS + col) =
                    make_float2(acc[mt][nt][2] + b0, acc[mt][nt][3] + b1);
            }
        }
    } else if (mode == 1) { // K -> g_k fp32
#pragma unroll
        for (int mt = 0; mt < 4; mt++) {
            int row0 = brow + wm*64 + mt*16 + g;
#pragma unroll
            for (int nt = 0; nt < 8; nt++) {
                int col = bcol + wn*64 + nt*8 + t2;
                float b0 = kb[col], b1 = kb[col + 1];
                *(float2*)(g_k + (size_t)row0 * KCOLS + col) =
                    make_float2(acc[mt][nt][0] + b0, acc[mt][nt][1] + b1);
                *(float2*)(g_k + (size_t)(row0 + 8) * KCOLS + col) =
                    make_float2(acc[mt][nt][2] + b0, acc[mt][nt][3] + b1);
            }
        }
    } else {                // V -> g_vh fp16 (fp32 acc+bias, then rn)
#pragma unroll
        for (int mt = 0; mt < 4; mt++) {
            int row0 = brow + wm*64 + mt*16 + g;
#pragma unroll
            for (int nt = 0; nt < 8; nt++) {
                int col = bcol + wn*64 + nt*8 + t2;
                float b0 = vb[col], b1 = vb[col + 1];
                *(__half2*)(g_vh + (size_t)row0 * KCOLS + col) =
                    __floats2half2_rn(acc[mt][nt][0] + b0, acc[mt][nt][1] + b1);
                *(__half2*)(g_vh + (size_t)(row0 + 8) * KCOLS + col) =
                    __floats2half2_rn(acc[mt][nt][2] + b0, acc[mt][nt][3] + b1);
            }
        }
    }
}

// ---- O-projection: fp32 out, no bias ----
__global__ __launch_bounds__(128, 2)
void gemm_h(const __half* __restrict__ A, const __half* __restrict__ B,
            float* __restrict__ C, int Ncols, int K)
{
    extern __shared__ __half smh[];
    const uint32_t sbase = (uint32_t)__cvta_generic_to_shared(smh);
    const int tid = threadIdx.x, lane = tid & 31;
    const int w = tid >> 5, wm = w >> 1, wn = w & 1;
    const int brow = blockIdx.x * 128, bcol = blockIdx.y * 128;

    float acc[4][8][4];
    gemm_mainloop(sbase, tid, lane, wm, wn, brow, bcol, A, B, Ncols, K, acc);

    const int g = lane >> 2, t2 = (lane & 3) * 2;
#pragma unroll
    for (int mt = 0; mt < 4; mt++) {
        int row0 = brow + wm*64 + mt*16 + g;
#pragma unroll
        for (int nt = 0; nt < 8; nt++) {
            int col = bcol + wn*64 + nt*8 + t2;
            *(float2*)(C + (size_t)row0 * Ncols + col) =
                make_float2(acc[mt][nt][0], acc[mt][nt][1]);
            *(float2*)(C + (size_t)(row0 + 8) * Ncols + col) =
                make_float2(acc[mt][nt][2], acc[mt][nt][3]);
        }
    }
}

// =====================================================================
// RoPE -> fp16 (scale folded for Q): layout (t, heads, 128), pair (h, h+64)
// =====================================================================
__global__ __launch_bounds__(256)
void rope_h_kernel(const float* __restrict__ src, __half* __restrict__ dst,
                   const float* __restrict__ sinp, const float* __restrict__ cosp,
                   int heads, float scale)
{
    int idx = blockIdx.x * blockDim.x + threadIdx.x;
    int total = T_LEN * heads * 64;
    if (idx >= total) return;
    int h = idx & 63;
    int tmp = idx >> 6;
    int n = tmp % heads;
    int t = tmp / heads;
    float s = sinp[t * 64 + h];
    float c = cosp[t * 64 + h];
    size_t p = ((size_t)t * heads + n) * HD + h;
    float x1 = src[p], x2 = src[p + 64];
    dst[p]      = __float2half((x1 * c - x2 * s) * scale);
    dst[p + 64] = __float2half((x2 * c + x1 * s) * scale);
}

// =====================================================================
// fp16 flash attention.  BM=128, BN=64, 8 warps; Q + P in registers;
// K ldmatrix, V ldmatrix.trans; K/V 3-stage cp.async.
// Heavy row-blocks scheduled first (br reversed) for causal load balance.
// grid = (T/128, NHEADS)
// =====================================================================
#define QBYTES  (128 * 136 * 2)     // 34816
#define KVSTG   (2 * 64 * 136 * 2)  // 34816
#define FLASH_SMEM (QBYTES + 3 * KVSTG)   // 139264

__global__ __launch_bounds__(256, 1)
void flash_h_kernel()
{
    extern __shared__ __half smf[];
    const uint32_t sbase = (uint32_t)__cvta_generic_to_shared(smf);
    const int br = gridDim.x - 1 - blockIdx.x;   // heavy blocks first
    const int n = blockIdx.y, kh = n / GRP;
    const int tid = threadIdx.x, lane = tid & 31;
    const int g = lane >> 2, t2 = (lane & 3) * 2;
    const int w = tid >> 5, rowbase = w * 16;

    auto issue_kv = [&](int j, int s) {
        const __half* Kg = g_kh + (size_t)(j * 64) * KCOLS + kh * HD;
        const __half* Vg = g_vh + (size_t)(j * 64) * KCOLS + kh * HD;
        uint32_t Kb = sbase + QBYTES + (uint32_t)(s * KVSTG);
        uint32_t Vb = Kb + 64 * 136 * 2;
#pragma unroll
        for (int i = 0; i < 4; i++) {
            int f = tid + i * 256;
            int r = f >> 4, c = (f & 15) * 8;
            cpa16(Kb + (uint32_t)(r * 136 + c) * 2, Kg + (size_t)r * KCOLS + c);
        }
#pragma unroll
        for (int i = 0; i < 4; i++) {
            int f = tid + i * 256;
            int r = f >> 4, c = (f & 15) * 8;
            cpa16(Vb + (uint32_t)(r * 136 + c) * 2, Vg + (size_t)r * KCOLS + c);
        }
        asm volatile("cp.async.commit_group;");
    };

    const int jmax = 2 * br + 1;

    // ---- prologue: Q + first two KV tiles ----
    {
        const __half* Qg = g_qh + (size_t)(br * 128) * QCOLS + n * HD;
#pragma unroll
        for (int i = 0; i < 8; i++) {
            int f = tid + i * 256;
            int r = f >> 4, c = (f & 15) * 8;
            cpa16(sbase + (uint32_t)(r * 136 + c) * 2, Qg + (size_t)r * QCOLS + c);
        }
        asm volatile("cp.async.commit_group;");
    }
    issue_kv(0, 0);
    issue_kv(1, 1);
    asm volatile("cp.async.wait_group 2;" ::: "memory");   // Q done
    __syncthreads();

    uint32_t qf[8][4];
#pragma unroll
    for (int kk = 0; kk < 8; kk++)
        ldm4(qf[kk], sbase + (uint32_t)((rowbase + (lane & 15)) * 136
                                        + kk * 16 + (lane >> 4) * 8) * 2);

    float m0 = -1e30f, m1 = -1e30f, l0 = 0.f, l1 = 0.f;
    float acc[16][4];
#pragma unroll
    for (int nt = 0; nt < 16; nt++)
#pragma unroll
        for (int r = 0; r < 4; r++) acc[nt][r] = 0.f;

    for (int j = 0; j <= jmax; ++j) {
        if (j < jmax) asm volatile("cp.async.wait_group 1;" ::: "memory");
        else          asm volatile("cp.async.wait_group 0;" ::: "memory");
        __syncthreads();
        if (j + 2 <= jmax) issue_kv(j + 2, (j + 2) % 3);

        uint32_t Kb = sbase + QBYTES + (uint32_t)((j % 3) * KVSTG);
        uint32_t Vb = Kb + 64 * 136 * 2;

        // ---- S = Q K^T ----
        float s_acc[8][4];
#pragma unroll
        for (int nt = 0; nt < 8; nt++)
#pragma unroll
            for (int r = 0; r < 4; r++) s_acc[nt][r] = 0.f;

#pragma unroll
        for (int kk = 0; kk < 8; kk++) {
            const int koff = kk * 16 + (lane >> 4) * 8;
#pragma unroll
            for (int nb = 0; nb < 4; nb++) {
                uint32_t bk[4];
                ldm4(bk, Kb + (uint32_t)((nb*16 + (lane & 15)) * 136 + koff) * 2);
                mma16(s_acc[nb*2+0], qf[kk], bk[0], bk[2]);
                mma16(s_acc[nb*2+1], qf[kk], bk[1], bk[3]);
            }
        }

        // ---- causal mask (boundary tiles only) ----
        if (j >= 2 * br) {
            int q0r = br * 128 + rowbase + g;
            int q1r = q0r + 8;
            int kb0 = j * 64;
#pragma unroll
            for (int nt = 0; nt < 8; nt++) {
                int c0 = kb0 + nt * 8 + t2, c1 = c0 + 1;
                if (c0 > q0r) s_acc[nt][0] = -1e30f;
                if (c1 > q0r) s_acc[nt][1] = -1e30f;
                if (c0 > q1r) s_acc[nt][2] = -1e30f;
                if (c1 > q1r) s_acc[nt][3] = -1e30f;
            }
        }

        // ---- online softmax ----
        float rmax0 = -1e30f, rmax1 = -1e30f;
#pragma unroll
        for (int nt = 0; nt < 8; nt++) {
            rmax0 = fmaxf(rmax0, fmaxf(s_acc[nt][0], s_acc[nt][1]));
            rmax1 = fmaxf(rmax1, fmaxf(s_acc[nt][2], s_acc[nt][3]));
        }
        rmax0 = fmaxf(rmax0, __shfl_xor_sync(0xffffffffu, rmax0, 1));
        rmax0 = fmaxf(rmax0, __shfl_xor_sync(0xffffffffu, rmax0, 2));
        rmax1 = fmaxf(rmax1, __shfl_xor_sync(0xffffffffu, rmax1, 1));
        rmax1 = fmaxf(rmax1, __shfl_xor_sync(0xffffffffu, rmax1, 2));
        float mn0 = fmaxf(m0, rmax0), mn1 = fmaxf(m1, rmax1);
        float alpha0 = __expf(m0 - mn0), alpha1 = __expf(m1 - mn1);

        uint32_t pa[4][4];
        float sum0 = 0.f, sum1 = 0.f;
#pragma unroll
        for (int nt = 0; nt < 8; nt++) {
            float e0 = __expf(s_acc[nt][0] - mn0);
            float e1 = __expf(s_acc[nt][1] - mn0);
            float e2 = __expf(s_acc[nt][2] - mn1);
            float e3 = __expf(s_acc[nt][3] - mn1);
            sum0 += e0 + e1;  sum1 += e2 + e3;
            const int kk2 = nt >> 1, hi = (nt & 1) * 2;
            pa[kk2][hi + 0] = h2u(e0, e1);
            pa[kk2][hi + 1] = h2u(e2, e3);
        }
        sum0 += __shfl_xor_sync(0xffffffffu, sum0, 1);
        sum0 += __shfl_xor_sync(0xffffffffu, sum0, 2);
        sum1 += __shfl_xor_sync(0xffffffffu, sum1, 1);
        sum1 += __shfl_xor_sync(0xffffffffu, sum1, 2);
        l0 = l0 * alpha0 + sum0;  m0 = mn0;
        l1 = l1 * alpha1 + sum1;  m1 = mn1;
#pragma unroll
        for (int nt = 0; nt < 16; nt++) {
            acc[nt][0] *= alpha0;  acc[nt][1] *= alpha0;
            acc[nt][2] *= alpha1;  acc[nt][3] *= alpha1;
        }

        // ---- O += P V  (V via ldmatrix.trans) ----
#pragma unroll
        for (int kk2 = 0; kk2 < 4; kk2++) {
            const int srow = kk2 * 16 + ((lane >> 3) & 1) * 8 + (lane & 7);
            const int dofb = (lane >> 4) * 8;
#pragma unroll
            for (int db = 0; db < 8; db++) {
                uint32_t bv[4];
                ldm4t(bv, Vb + (uint32_t)(srow * 136 + db * 16 + dofb) * 2);
                mma16(acc[db*2+0], pa[kk2], bv[0], bv[1]);
                mma16(acc[db*2+1], pa[kk2], bv[2], bv[3]);
            }
        }
    }

    // ---- epilogue: fp16 to g_aoh ----
    float rl0 = 1.f / l0, rl1 = 1.f / l1;
    int row0 = br * 128 + rowbase + g;
    __half* op0 = g_aoh + (size_t)row0 * QCOLS + n * HD;
    __half* op1 = op0 + (size_t)8 * QCOLS;
#pragma unroll
    for (int nt = 0; nt < 16; nt++) {
        int col = nt * 8 + t2;
        *(__half2*)(op0 + col) = __floats2half2_rn(acc[nt][0] * rl0, acc[nt][1] * rl0);
        *(__half2*)(op1 + col) = __floats2half2_rn(acc[nt][2] * rl1, acc[nt][3] * rl1);
    }
}

// =====================================================================
extern "C" void kernel_launch(void* const* d_in, const int* in_sizes, int n_in,
                              void* d_out, int out_size)
{
    const float* x    = (const float*)d_in[0];
    const float* sinp = (const float*)d_in[2];
    const float* cosp = (const float*)d_in[3];
    const float* wq   = (const float*)d_in[4];
    const float* wk   = (const float*)d_in[5];
    const float* wv   = (const float*)d_in[6];
    const float* wo   = (const float*)d_in[7];
    const float* qb   = (const float*)d_in[8];
    const float* kb   = (const float*)d_in[9];
    const float* vb   = (const float*)d_in[10];
    float* out = (float*)d_out;

    float *qp, *kp;
    __half *xh, *wqh, *wkh, *wvh, *woh, *qh, *kkh, *aoh;
    cudaGetSymbolAddress((void**)&qp,  g_q);
    cudaGetSymbolAddress((void**)&kp,  g_k);
    cudaGetSymbolAddress((void**)&xh,  g_xh);
    cudaGetSymbolAddress((void**)&wqh, g_wqh);
    cudaGetSymbolAddress((void**)&wkh, g_wkh);
    cudaGetSymbolAddress((void**)&wvh, g_wvh);
    cudaGetSymbolAddress((void**)&woh, g_woh);
    cudaGetSymbolAddress((void**)&qh,  g_qh);
    cudaGetSymbolAddress((void**)&kkh, g_kh);
    cudaGetSymbolAddress((void**)&aoh, g_aoh);

    cudaFuncSetAttribute(gemm_qkv,
                         cudaFuncAttributeMaxDynamicSharedMemorySize, GEMM_SMEM);
    cudaFuncSetAttribute(gemm_h,
                         cudaFuncAttributeMaxDynamicSharedMemorySize, GEMM_SMEM);
    cudaFuncSetAttribute(flash_h_kernel,
                         cudaFuncAttributeMaxDynamicSharedMemorySize, FLASH_SMEM);

    // ---- prepass: fp16 conversions only (no transposes) ----
    cvt_h_kernel<<<(T_LEN*D_DIM/4 + 255)/256, 256>>>(x,  xh,  T_LEN*D_DIM/4);
    cvt_h_kernel<<<(D_DIM*QCOLS/4 + 255)/256, 256>>>(wq, wqh, D_DIM*QCOLS/4);
    cvt_h_kernel<<<(D_DIM*KCOLS/4 + 255)/256, 256>>>(wk, wkh, D_DIM*KCOLS/4);
    cvt_h_kernel<<<(D_DIM*KCOLS/4 + 255)/256, 256>>>(wv, wvh, D_DIM*KCOLS/4);
    cvt_h_kernel<<<(QCOLS*D_DIM/4 + 255)/256, 256>>>(wo, woh, QCOLS*D_DIM/4);

    // ---- fused QKV projection (V written fp16 directly) ----
    gemm_qkv<<<dim3(T_LEN/128, 36), 128, GEMM_SMEM>>>(xh, qb, kb, vb);

    // ---- RoPE -> fp16 (Q pre-scaled) ----
    rope_h_kernel<<<(T_LEN*NHEADS*64 + 255)/256, 256>>>(qp, qh, sinp, cosp, NHEADS, SCALE_ATTN);
    rope_h_kernel<<<(T_LEN*KVH*64 + 255)/256, 256>>>(kp, kkh, sinp, cosp, KVH, 1.0f);

    // ---- flash attention (heavy blocks first) ----
    flash_h_kernel<<<dim3(T_LEN/128, NHEADS), 256, FLASH_SMEM>>>();

    // ---- output projection -> d_out ----
    gemm_h<<<dim3(T_LEN/128, D_DIM/128), 128, GEMM_SMEM>>>(aoh, woh, out, D_DIM, QCOLS);
}

// round 13
// speedup vs baseline: 11.3460x; 1.0453x over previous
#include <cuda_runtime.h>
#include <cuda_fp16.h>
#include <cstddef>
#include <cstdint>

#define T_LEN   2048
#define D_DIM   3584
#define NHEADS  28
#define KVH     4
#define HD      128
#define GRP     7
#define QCOLS   (NHEADS*HD)   // 3584
#define KCOLS   (KVH*HD)      // 512
#define SCALE_ATTN 0.08838834764831845f

// -------- scratch (no cudaMalloc allowed) --------
__device__ __half g_xh [T_LEN * D_DIM];          // x fp16
__device__ __half g_wqh[D_DIM * QCOLS];          // wq fp16 (K-major natural layout)
__device__ __half g_wkh[D_DIM * KCOLS];
__device__ __half g_wvh[D_DIM * KCOLS];
__device__ __half g_woh[QCOLS * D_DIM];          // wo fp16 [nh][d]
__device__ __half g_qh [T_LEN * QCOLS];          // rope(Q)*scale fp16
__device__ __half g_kh [T_LEN * KCOLS];          // rope(K) fp16
__device__ __half g_vh [T_LEN * KCOLS];          // V fp16
__device__ __half g_aoh[T_LEN * QCOLS];          // attention out fp16

// ---------------- helpers ----------------
__device__ __forceinline__ void cpa16(uint32_t dst, const void* src) {
    asm volatile("cp.async.cg.shared.global [%0], [%1], 16;" :: "r"(dst), "l"(src));
}
__device__ __forceinline__ void ldm4(uint32_t* r, uint32_t a) {
    asm volatile("ldmatrix.sync.aligned.m8n8.x4.shared.b16 {%0,%1,%2,%3}, [%4];"
                 : "=r"(r[0]), "=r"(r[1]), "=r"(r[2]), "=r"(r[3]) : "r"(a));
}
__device__ __forceinline__ void ldm4t(uint32_t* r, uint32_t a) {
    asm volatile("ldmatrix.sync.aligned.m8n8.x4.trans.shared.b16 {%0,%1,%2,%3}, [%4];"
                 : "=r"(r[0]), "=r"(r[1]), "=r"(r[2]), "=r"(r[3]) : "r"(a));
}
__device__ __forceinline__ void mma16(float* c, const uint32_t* a, uint32_t b0, uint32_t b1) {
    asm volatile(
        "mma.sync.aligned.m16n8k16.row.col.f32.f16.f16.f32 "
        "{%0,%1,%2,%3}, {%4,%5,%6,%7}, {%8,%9}, {%0,%1,%2,%3};"
        : "+f"(c[0]), "+f"(c[1]), "+f"(c[2]), "+f"(c[3])
        : "r"(a[0]), "r"(a[1]), "r"(a[2]), "r"(a[3]), "r"(b0), "r"(b1));
}
__device__ __forceinline__ uint32_t h2u(float a, float b) {
    __half2 h = __floats2half2_rn(a, b);
    return *reinterpret_cast<uint32_t*>(&h);
}

// =====================================================================
// prepass: fp32 -> fp16
// =====================================================================
__global__ __launch_bounds__(256)
void cvt_h_kernel(const float* __restrict__ s, __half* __restrict__ d, int n4)
{
    int i = blockIdx.x * blockDim.x + threadIdx.x;
    if (i >= n4) return;
    float4 v = ((const float4*)s)[i];
    ((__half2*)d)[2*i]   = __floats2half2_rn(v.x, v.y);
    ((__half2*)d)[2*i+1] = __floats2half2_rn(v.z, v.w);
}

// =====================================================================
// GEMM mainloop: CTA 128x128, BK=32, 3-stage cp.async, 128 threads,
// 4 warps (2x2), warp tile 64x64.  B K-major, consumed via ldmatrix.trans.
// =====================================================================
#define ABYT 10240                        // A: 128 x 40 halfs x 2B
#define GSTGB (ABYT + 32*136*2)           // 18944 per stage
#define STG_STRIDE 132
#define GEMM_SMEM (128 * STG_STRIDE * 4)  // 67584 >= 3*GSTGB (56832); epilogue staging

__device__ __forceinline__ void gemm_mainloop(
    uint32_t sbase, int tid, int lane, int wm, int wn, int brow, int bcol,
    const __half* __restrict__ A, const __half* __restrict__ B,
    int Ncols, int K, float acc[4][8][4])
{
#pragma unroll
    for (int mt = 0; mt < 4; mt++)
#pragma unroll
        for (int nt = 0; nt < 8; nt++)
#pragma unroll
            for (int r = 0; r < 4; r++) acc[mt][nt][r] = 0.f;

    const int nIter = K / 32;

    auto issue = [&](int it, int s) {
        const int k0 = it * 32;
        uint32_t ab = sbase + (uint32_t)(s * GSTGB);
        uint32_t bb = ab + ABYT;
#pragma unroll
        for (int i = 0; i < 4; i++) {
            int f = tid + i * 128;
            int m = f >> 2, c = (f & 3) * 8;
            cpa16(ab + (uint32_t)(m * 40 + c) * 2, A + (size_t)(brow + m) * K + k0 + c);
        }
#pragma unroll
        for (int i = 0; i < 4; i++) {
            int f = tid + i * 128;
            int kr = f >> 4, nc = (f & 15) * 8;
            cpa16(bb + (uint32_t)(kr * 136 + nc) * 2, B + (size_t)(k0 + kr) * Ncols + bcol + nc);
        }
        asm volatile("cp.async.commit_group;");
    };

    issue(0, 0);
    issue(1, 1);

    const int dofb = (lane >> 4) * 8;
    const int srb  = ((lane >> 3) & 1) * 8 + (lane & 7);

    for (int it = 0; it < nIter; ++it) {
        if (it < nIter - 1) asm volatile("cp.async.wait_group 1;" ::: "memory");
        else                asm volatile("cp.async.wait_group 0;" ::: "memory");
        __syncthreads();
        if (it + 2 < nIter) issue(it + 2, (it + 2) % 3);

        uint32_t ab = sbase + (uint32_t)((it % 3) * GSTGB);
        uint32_t bb = ab + ABYT;
#pragma unroll
        for (int ks = 0; ks < 2; ks++) {
            const int koff = ks * 16;
            uint32_t a[4][4];
#pragma unroll
            for (int mt = 0; mt < 4; mt++)
                ldm4(a[mt], ab + (uint32_t)((wm*64 + mt*16 + (lane & 15)) * 40
                                            + koff + dofb) * 2);
#pragma unroll
            for (int db = 0; db < 4; db++) {
                uint32_t bv[4];
                ldm4t(bv, bb + (uint32_t)((koff + srb) * 136
                                          + wn*64 + db*16 + dofb) * 2);
#pragma unroll
                for (int mt = 0; mt < 4; mt++) {
                    mma16(acc[mt][db*2+0], a[mt], bv[0], bv[1]);
                    mma16(acc[mt][db*2+1], a[mt], bv[2], bv[3]);
                }
            }
        }
    }
}

// ---- fused QKV projection with in-epilogue RoPE ----
// by < 28: Q head by -> rope*scale -> g_qh ; by 28-31: K head -> rope -> g_kh ;
// by 32-35: V -> g_vh (fp16 direct).
__global__ __launch_bounds__(128, 2)
void gemm_qkv(const __half* __restrict__ A,
              const float* __restrict__ qb, const float* __restrict__ kb,
              const float* __restrict__ vb,
              const float* __restrict__ sinp, const float* __restrict__ cosp)
{
    extern __shared__ __half smh[];
    const uint32_t sbase = (uint32_t)__cvta_generic_to_shared(smh);
    const int tid = threadIdx.x, lane = tid & 31;
    const int w = tid >> 5, wm = w >> 1, wn = w & 1;
    const int brow = blockIdx.x * 128;
    const int by = blockIdx.y;

    const __half* B;
    int bcol, Ncols, mode;
    if (by < 28)      { B = g_wqh; bcol = by * 128;        Ncols = QCOLS; mode = 0; }
    else if (by < 32) { B = g_wkh; bcol = (by - 28) * 128; Ncols = KCOLS; mode = 1; }
    else              { B = g_wvh; bcol = (by - 32) * 128; Ncols = KCOLS; mode = 2; }

    float acc[4][8][4];
    gemm_mainloop(sbase, tid, lane, wm, wn, brow, bcol, A, B, Ncols, D_DIM, acc);

    const int g = lane >> 2, t2 = (lane & 3) * 2;
    const float* bias = (mode == 0) ? qb : (mode == 1) ? kb : vb;

    if (mode == 2) {        // V -> g_vh fp16 (fp32 acc+bias, then rn)
#pragma unroll
        for (int mt = 0; mt < 4; mt++) {
            int row0 = brow + wm*64 + mt*16 + g;
#pragma unroll
            for (int nt = 0; nt < 8; nt++) {
                int col = bcol + wn*64 + nt*8 + t2;
                float b0 = bias[col], b1 = bias[col + 1];
                *(__half2*)(g_vh + (size_t)row0 * KCOLS + col) =
                    __floats2half2_rn(acc[mt][nt][0] + b0, acc[mt][nt][1] + b1);
                *(__half2*)(g_vh + (size_t)(row0 + 8) * KCOLS + col) =
                    __floats2half2_rn(acc[mt][nt][2] + b0, acc[mt][nt][3] + b1);
            }
        }
        return;
    }

    // ---- Q/K: stage fp32 acc+bias in smem, then rope -> fp16 ----
    float* stg = (float*)smh;      // [128][STG_STRIDE], reuses pipeline smem
    __syncthreads();               // all mainloop smem reads complete
#pragma unroll
    for (int mt = 0; mt < 4; mt++) {
        int rl0 = wm*64 + mt*16 + g;
#pragma unroll
        for (int nt = 0; nt < 8; nt++) {
            int cl = wn*64 + nt*8 + t2;
            float b0 = bias[bcol + cl], b1 = bias[bcol + cl + 1];
            *(float2*)(stg + rl0 * STG_STRIDE + cl) =
                make_float2(acc[mt][nt][0] + b0, acc[mt][nt][1] + b1);
            *(float2*)(stg + (rl0 + 8) * STG_STRIDE + cl) =
                make_float2(acc[mt][nt][2] + b0, acc[mt][nt][3] + b1);
        }
    }
    __syncthreads();

    __half* dst = (mode == 0) ? g_qh : g_kh;
    const float scale = (mode == 0) ? SCALE_ATTN : 1.0f;
    const int h2 = (lane & 31) * 2;              // wait: need 0..62 over 32 lanes
    // thread mapping: 128 threads = 4 rows x 32 col-pairs per step, 32 steps
    const int cpair = (tid & 31) * 2;            // 0,2,..,62
    const int rsub  = tid >> 5;                  // 0..3
    (void)h2;
#pragma unroll 4
    for (int step = 0; step < 32; ++step) {
        int rl = step * 4 + rsub;
        int t  = brow + rl;
        float x1a = stg[rl * STG_STRIDE + cpair];
        float x1b = stg[rl * STG_STRIDE + cpair + 1];
        float x2a = stg[rl * STG_STRIDE + cpair + 64];
        float x2b = stg[rl * STG_STRIDE + cpair + 65];
        float2 sv = *(const float2*)(sinp + t * 64 + cpair);
        float2 cv = *(const float2*)(cosp + t * 64 + cpair);
        *(__half2*)(dst + (size_t)t * Ncols + bcol + cpair) =
            __floats2half2_rn((x1a * cv.x - x2a * sv.x) * scale,
                              (x1b * cv.y - x2b * sv.y) * scale);
        *(__half2*)(dst + (size_t)t * Ncols + bcol + cpair + 64) =
            __floats2half2_rn((x2a * cv.x + x1a * sv.x) * scale,
                              (x2b * cv.y + x1b * sv.y) * scale);
    }
}

// ---- O-projection: fp32 out, no bias ----
__global__ __launch_bounds__(128, 2)
void gemm_h(const __half* __restrict__ A, const __half* __restrict__ B,
            float* __restrict__ C, int Ncols, int K)
{
    extern __shared__ __half smh[];
    const uint32_t sbase = (uint32_t)__cvta_generic_to_shared(smh);
    const int tid = threadIdx.x, lane = tid & 31;
    const int w = tid >> 5, wm = w >> 1, wn = w & 1;
    const int brow = blockIdx.x * 128, bcol = blockIdx.y * 128;

    float acc[4][8][4];
    gemm_mainloop(sbase, tid, lane, wm, wn, brow, bcol, A, B, Ncols, K, acc);

    const int g = lane >> 2, t2 = (lane & 3) * 2;
#pragma unroll
    for (int mt = 0; mt < 4; mt++) {
        int row0 = brow + wm*64 + mt*16 + g;
#pragma unroll
        for (int nt = 0; nt < 8; nt++) {
            int col = bcol + wn*64 + nt*8 + t2;
            *(float2*)(C + (size_t)row0 * Ncols + col) =
                make_float2(acc[mt][nt][0], acc[mt][nt][1]);
            *(float2*)(C + (size_t)(row0 + 8) * Ncols + col) =
                make_float2(acc[mt][nt][2], acc[mt][nt][3]);
        }
    }
}

// =====================================================================
// fp16 flash attention.  BM=128, BN=64, 8 warps; Q + P in registers;
// K ldmatrix, V ldmatrix.trans; K/V 3-stage cp.async; heavy blocks first.
// grid = (T/128, NHEADS)
// =====================================================================
#define QBYTES  (128 * 136 * 2)     // 34816
#define KVSTG   (2 * 64 * 136 * 2)  // 34816
#define FLASH_SMEM (QBYTES + 3 * KVSTG)   // 139264

__global__ __launch_bounds__(256, 1)
void flash_h_kernel()
{
    extern __shared__ __half smf[];
    const uint32_t sbase = (uint32_t)__cvta_generic_to_shared(smf);
    const int br = gridDim.x - 1 - blockIdx.x;   // heavy blocks first
    const int n = blockIdx.y, kh = n / GRP;
    const int tid = threadIdx.x, lane = tid & 31;
    const int g = lane >> 2, t2 = (lane & 3) * 2;
    const int w = tid >> 5, rowbase = w * 16;

    auto issue_kv = [&](int j, int s) {
        const __half* Kg = g_kh + (size_t)(j * 64) * KCOLS + kh * HD;
        const __half* Vg = g_vh + (size_t)(j * 64) * KCOLS + kh * HD;
        uint32_t Kb = sbase + QBYTES + (uint32_t)(s * KVSTG);
        uint32_t Vb = Kb + 64 * 136 * 2;
#pragma unroll
        for (int i = 0; i < 4; i++) {
            int f = tid + i * 256;
            int r = f >> 4, c = (f & 15) * 8;
            cpa16(Kb + (uint32_t)(r * 136 + c) * 2, Kg + (size_t)r * KCOLS + c);
        }
#pragma unroll
        for (int i = 0; i < 4; i++) {
            int f = tid + i * 256;
            int r = f >> 4, c = (f & 15) * 8;
            cpa16(Vb + (uint32_t)(r * 136 + c) * 2, Vg + (size_t)r * KCOLS + c);
        }
        asm volatile("cp.async.commit_group;");
    };

    const int jmax = 2 * br + 1;

    {
        const __half* Qg = g_qh + (size_t)(br * 128) * QCOLS + n * HD;
#pragma unroll
        for (int i = 0; i < 8; i++) {
            int f = tid + i * 256;
            int r = f >> 4, c = (f & 15) * 8;
            cpa16(sbase + (uint32_t)(r * 136 + c) * 2, Qg + (size_t)r * QCOLS + c);
        }
        asm volatile("cp.async.commit_group;");
    }
    issue_kv(0, 0);
    issue_kv(1, 1);
    asm volatile("cp.async.wait_group 2;" ::: "memory");
    __syncthreads();

    uint32_t qf[8][4];
#pragma unroll
    for (int kk = 0; kk < 8; kk++)
        ldm4(qf[kk], sbase + (uint32_t)((rowbase + (lane & 15)) * 136
                                        + kk * 16 + (lane >> 4) * 8) * 2);

    float m0 = -1e30f, m1 = -1e30f, l0 = 0.f, l1 = 0.f;
    float acc[16][4];
#pragma unroll
    for (int nt = 0; nt < 16; nt++)
#pragma unroll
        for (int r = 0; r < 4; r++) acc[nt][r] = 0.f;

    for (int j = 0; j <= jmax; ++j) {
        if (j < jmax) asm volatile("cp.async.wait_group 1;" ::: "memory");
        else          asm volatile("cp.async.wait_group 0;" ::: "memory");
        __syncthreads();
        if (j + 2 <= jmax) issue_kv(j + 2, (j + 2) % 3);

        uint32_t Kb = sbase + QBYTES + (uint32_t)((j % 3) * KVSTG);
        uint32_t Vb = Kb + 64 * 136 * 2;

        float s_acc[8][4];
#pragma unroll
        for (int nt = 0; nt < 8; nt++)
#pragma unroll
            for (int r = 0; r < 4; r++) s_acc[nt][r] = 0.f;

#pragma unroll
        for (int kk = 0; kk < 8; kk++) {
            const int koff = kk * 16 + (lane >> 4) * 8;
#pragma unroll
            for (int nb = 0; nb < 4; nb++) {
                uint32_t bk[4];
                ldm4(bk, Kb + (uint32_t)((nb*16 + (lane & 15)) * 136 + koff) * 2);
                mma16(s_acc[nb*2+0], qf[kk], bk[0], bk[2]);
                mma16(s_acc[nb*2+1], qf[kk], bk[1], bk[3]);
            }
        }

        if (j >= 2 * br) {
            int q0r = br * 128 + rowbase + g;
            int q1r = q0r + 8;
            int kb0 = j * 64;
#pragma unroll
            for (int nt = 0; nt < 8; nt++) {
                int c0 = kb0 + nt * 8 + t2, c1 = c0 + 1;
                if (c0 > q0r) s_acc[nt][0] = -1e30f;
                if (c1 > q0r) s_acc[nt][1] = -1e30f;
                if (c0 > q1r) s_acc[nt][2] = -1e30f;
                if (c1 > q1r) s_acc[nt][3] = -1e30f;
            }
        }

        float rmax0 = -1e30f, rmax1 = -1e30f;
#pragma unroll
        for (int nt = 0; nt < 8; nt++) {
            rmax0 = fmaxf(rmax0, fmaxf(s_acc[nt][0], s_acc[nt][1]));
            rmax1 = fmaxf(rmax1, fmaxf(s_acc[nt][2], s_acc[nt][3]));
        }
        rmax0 = fmaxf(rmax0, __shfl_xor_sync(0xffffffffu, rmax0, 1));
        rmax0 = fmaxf(rmax0, __shfl_xor_sync(0xffffffffu, rmax0, 2));
        rmax1 = fmaxf(rmax1, __shfl_xor_sync(0xffffffffu, rmax1, 1));
        rmax1 = fmaxf(rmax1, __shfl_xor_sync(0xffffffffu, rmax1, 2));
        float mn0 = fmaxf(m0, rmax0), mn1 = fmaxf(m1, rmax1);
        float alpha0 = __expf(m0 - mn0), alpha1 = __expf(m1 - mn1);

        uint32_t pa[4][4];
        float sum0 = 0.f, sum1 = 0.f;
#pragma unroll
        for (int nt = 0; nt < 8; nt++) {
            float e0 = __expf(s_acc[nt][0] - mn0);
            float e1 = __expf(s_acc[nt][1] - mn0);
            float e2 = __expf(s_acc[nt][2] - mn1);
            float e3 = __expf(s_acc[nt][3] - mn1);
            sum0 += e0 + e1;  sum1 += e2 + e3;
            const int kk2 = nt >> 1, hi = (nt & 1) * 2;
            pa[kk2][hi + 0] = h2u(e0, e1);
            pa[kk2][hi + 1] = h2u(e2, e3);
        }
        sum0 += __shfl_xor_sync(0xffffffffu, sum0, 1);
        sum0 += __shfl_xor_sync(0xffffffffu, sum0, 2);
        sum1 += __shfl_xor_sync(0xffffffffu, sum1, 1);
        sum1 += __shfl_xor_sync(0xffffffffu, sum1, 2);
        l0 = l0 * alpha0 + sum0;  m0 = mn0;
        l1 = l1 * alpha1 + sum1;  m1 = mn1;
#pragma unroll
        for (int nt = 0; nt < 16; nt++) {
            acc[nt][0] *= alpha0;  acc[nt][1] *= alpha0;
            acc[nt][2] *= alpha1;  acc[nt][3] *= alpha1;
        }

#pragma unroll
        for (int kk2 = 0; kk2 < 4; kk2++) {
            const int srow = kk2 * 16 + ((lane >> 3) & 1) * 8 + (lane & 7);
            const int dofb = (lane >> 4) * 8;
#pragma unroll
            for (int db = 0; db < 8; db++) {
                uint32_t bv[4];
                ldm4t(bv, Vb + (uint32_t)(srow * 136 + db * 16 + dofb) * 2);
                mma16(acc[db*2+0], pa[kk2], bv[0], bv[1]);
                mma16(acc[db*2+1], pa[kk2], bv[2], bv[3]);
            }
        }
    }

    float rl0 = 1.f / l0, rl1 = 1.f / l1;
    int row0 = br * 128 + rowbase + g;
    __half* op0 = g_aoh + (size_t)row0 * QCOLS + n * HD;
    __half* op1 = op0 + (size_t)8 * QCOLS;
#pragma unroll
    for (int nt = 0; nt < 16; nt++) {
        int col = nt * 8 + t2;
        *(__half2*)(op0 + col) = __floats2half2_rn(acc[nt][0] * rl0, acc[nt][1] * rl0);
        *(__half2*)(op1 + col) = __floats2half2_rn(acc[nt][2] * rl1, acc[nt][3] * rl1);
    }
}

// =====================================================================
extern "C" void kernel_launch(void* const* d_in, const int* in_sizes, int n_in,
                              void* d_out, int out_size)
{
    const float* x    = (const float*)d_in[0];
    const float* sinp = (const float*)d_in[2];
    const float* cosp = (const float*)d_in[3];
    const float* wq   = (const float*)d_in[4];
    const float* wk   = (const float*)d_in[5];
    const float* wv   = (const float*)d_in[6];
    const float* wo   = (const float*)d_in[7];
    const float* qb   = (const float*)d_in[8];
    const float* kb   = (const float*)d_in[9];
    const float* vb   = (const float*)d_in[10];
    float* out = (float*)d_out;

    __half *xh, *wqh, *wkh, *wvh, *woh, *aoh;
    cudaGetSymbolAddress((void**)&xh,  g_xh);
    cudaGetSymbolAddress((void**)&wqh, g_wqh);
    cudaGetSymbolAddress((void**)&wkh, g_wkh);
    cudaGetSymbolAddress((void**)&wvh, g_wvh);
    cudaGetSymbolAddress((void**)&woh, g_woh);
    cudaGetSymbolAddress((void**)&aoh, g_aoh);

    cudaFuncSetAttribute(gemm_qkv,
                         cudaFuncAttributeMaxDynamicSharedMemorySize, GEMM_SMEM);
    cudaFuncSetAttribute(gemm_h,
                         cudaFuncAttributeMaxDynamicSharedMemorySize, GEMM_SMEM);
    cudaFuncSetAttribute(flash_h_kernel,
                         cudaFuncAttributeMaxDynamicSharedMemorySize, FLASH_SMEM);

    // ---- prepass: fp16 conversions ----
    cvt_h_kernel<<<(T_LEN*D_DIM/4 + 255)/256, 256>>>(x,  xh,  T_LEN*D_DIM/4);
    cvt_h_kernel<<<(D_DIM*QCOLS/4 + 255)/256, 256>>>(wq, wqh, D_DIM*QCOLS/4);
    cvt_h_kernel<<<(D_DIM*KCOLS/4 + 255)/256, 256>>>(wk, wkh, D_DIM*KCOLS/4);
    cvt_h_kernel<<<(D_DIM*KCOLS/4 + 255)/256, 256>>>(wv, wvh, D_DIM*KCOLS/4);
    cvt_h_kernel<<<(QCOLS*D_DIM/4 + 255)/256, 256>>>(wo, woh, QCOLS*D_DIM/4);

    // ---- fused QKV projection with in-epilogue RoPE ----
    gemm_qkv<<<dim3(T_LEN/128, 36), 128, GEMM_SMEM>>>(xh, qb, kb, vb, sinp, cosp);

    // ---- flash attention (heavy blocks first) ----
    flash_h_kernel<<<dim3(T_LEN/128, NHEADS), 256, FLASH_SMEM>>>();

    // ---- output projection -> d_out ----
    gemm_h<<<dim3(T_LEN/128, D_DIM/128), 128, GEMM_SMEM>>>(aoh, woh, out, D_DIM, QCOLS);
}